// round 11
// baseline (speedup 1.0000x reference)
#include <cuda_runtime.h>
#include <cuda_fp16.h>
#include <stdint.h>

#define NN 20000
#define NE 320000

// ---------------- static scratch (BSS zero-init gives free zero padding) ----------------
__device__ __half g_hA[(size_t)NN * 1024];
__device__ __half g_hB[(size_t)NN * 1024];
__device__ __half g_hC[(size_t)NN * 1024];
__device__ __half g_h16[(size_t)NN * 64];      // h padded 16 -> 64 cols
__device__ __half g_w16[5128192];              // transposed fp16 weights
__device__ float g_inv[NN];
__device__ int   g_cnti[NN];
__device__ int   g_fill[NN];
__device__ int   g_rowptr[NN + 1];
__device__ int   g_esrc[NE];
__device__ float2 g_erel[NE];
__device__ int   g_idx64;

// transposed fp16 weight offsets (halves). [Np][Kp] layouts.
#define O_L1W1 0          // 256 x 64   (real 128 x 16)
#define O_L1W2 16384      // 256 x 128
#define O_L2W1 49152      // 256 x 128
#define O_L2W2 81920      // 256 x 256
#define O_L3W1 147456     // 1024 x 256
#define O_L3W2 409600     // 1024 x 1024
#define O_L4W1 1458176
#define O_L4W2 2506752
#define O_HDW1 3555328
#define O_HDW2 4603904    // 512 x 1024

__device__ __forceinline__ void cp16(uint32_t dst, const void* src, bool v) {
    if (v)
        asm volatile("cp.async.cg.shared.global [%0], [%1], 16;" :: "r"(dst), "l"(src));
    else
        asm volatile("cp.async.cg.shared.global [%0], [%1], 16, 0;" :: "r"(dst), "l"(src));
}

#define LDSM_X4(r0, r1, r2, r3, addr) \
    asm volatile("ldmatrix.sync.aligned.m8n8.x4.shared.b16 {%0,%1,%2,%3}, [%4];" \
                 : "=r"(r0), "=r"(r1), "=r"(r2), "=r"(r3) : "r"(addr))

// ---------------- setup kernels ----------------
__global__ void detect_idx_kernel(const int* e) {
    if (threadIdx.x == 0 && blockIdx.x == 0) {
        int is64 = 1;
        for (int k = 0; k < 128; k++) {
            if (e[2 * k + 1] != 0) { is64 = 0; break; }
        }
        g_idx64 = is64;
    }
}

__global__ void zero2_int_kernel() {
    int i = blockIdx.x * blockDim.x + threadIdx.x;
    if (i < NN) { g_cnti[i] = 0; g_fill[i] = 0; }
}

__global__ void count_kernel(const void* eidx) {
    int e = blockIdx.x * blockDim.x + threadIdx.x;
    if (e >= NE) return;
    int d;
    if (g_idx64) d = (int)((const long long*)eidx)[(long long)NE + e];
    else         d = ((const int*)eidx)[NE + e];
    atomicAdd(&g_cnti[d], 1);
}

__global__ void scan_kernel() {
    __shared__ int part[1024];
    const int t = threadIdx.x;
    const int CH = 20;
    const int base = t * CH;
    int s = 0;
    for (int i = 0; i < CH; i++) {
        int idx = base + i;
        if (idx < NN) s += g_cnti[idx];
    }
    part[t] = s;
    __syncthreads();
    for (int off = 1; off < 1024; off <<= 1) {
        int v = 0;
        if (t >= off) v = part[t - off];
        __syncthreads();
        part[t] += v;
        __syncthreads();
    }
    int run = (t == 0) ? 0 : part[t - 1];
    for (int i = 0; i < CH; i++) {
        int idx = base + i;
        if (idx < NN) { g_rowptr[idx] = run; run += g_cnti[idx]; }
    }
    if (t == 1023) g_rowptr[NN] = part[1023];
}

__global__ void fill_kernel(const void* eidx, const float* __restrict__ pos) {
    int e = blockIdx.x * blockDim.x + threadIdx.x;
    if (e >= NE) return;
    int s, d;
    if (g_idx64) {
        s = (int)((const long long*)eidx)[e];
        d = (int)((const long long*)eidx)[(long long)NE + e];
    } else {
        s = ((const int*)eidx)[e];
        d = ((const int*)eidx)[NE + e];
    }
    int p = g_rowptr[d] + atomicAdd(&g_fill[d], 1);
    g_esrc[p] = s;
    g_erel[p] = make_float2(pos[2 * s] - pos[2 * d], pos[2 * s + 1] - pos[2 * d + 1]);
}

__global__ void make_inv_kernel() {
    int i = blockIdx.x * blockDim.x + threadIdx.x;
    if (i < NN) {
        int c = g_rowptr[i + 1] - g_rowptr[i];
        g_inv[i] = (c > 0) ? (1.f / (float)c) : 0.f;
    }
}

// W[K][N] fp32 -> WT[N][Kp] fp16 (zero-fill k in [Kreal, Kp))
__global__ void trconv_kernel(const float* __restrict__ src, __half* __restrict__ dst,
                              int Kreal, int N, int Kp)
{
    __shared__ float tile[32][33];
    const int bx = blockIdx.x * 32;  // n
    const int by = blockIdx.y * 32;  // k
    const int x = threadIdx.x, y = threadIdx.y;
    for (int i = 0; i < 32; i += 8) {
        int k = by + y + i, n = bx + x;
        tile[y + i][x] = (k < Kreal && n < N) ? src[(size_t)k * N + n] : 0.f;
    }
    __syncthreads();
    for (int i = 0; i < 32; i += 8) {
        int n = bx + y + i, k = by + x;
        if (n < N && k < Kp) dst[(size_t)n * Kp + k] = __float2half_rn(tile[x][y + i]);
    }
}

__global__ void convh_kernel(const float* __restrict__ h) {
    int idx = blockIdx.x * blockDim.x + threadIdx.x;
    if (idx >= NN * 16) return;
    int r = idx >> 4, c = idx & 15;
    g_h16[(size_t)r * 64 + c] = __float2half_rn(h[idx]);
}

// ---------------- fp16 MMA GEMM: 96x128 tile, BK=64, 2-stage, 2 CTAs/SM ----------------
// 8 warps as 2x4, warp tile 48x32 (acc 48 regs/thread).
#define HPITCHB 144                     // bytes per smem row (72 halves)
#define HASTG  (96 * HPITCHB)           // 13824
#define HBSTG  (128 * HPITCHB)          // 18432
#define HSTAGE (HASTG + HBSTG)          // 32256
#define HSMEM_BYTES (2 * HSTAGE)        // 64512 per CTA -> 2 CTAs/SM

__global__ void __launch_bounds__(256, 2)
hgemm_kernel(const __half* __restrict__ A, const __half* __restrict__ Bt,
             const float* __restrict__ bias, const float* __restrict__ rowscale,
             __half* __restrict__ C, int M, int N, int K, int doRelu)
{
    extern __shared__ char smemc[];
    const uint32_t sBase = (uint32_t)__cvta_generic_to_shared(smemc);

    const int tid = threadIdx.x;
    const int wid = tid >> 5, lane = tid & 31;
    const int wr = wid >> 2, wc = wid & 3;
    const int mW = wr * 48, nW = wc * 32;
    const int g = lane >> 2, t = lane & 3;
    const int q = lane >> 3, r = lane & 7;
    const int rowBase = blockIdx.y * 96;
    const int colBase = blockIdx.x * 128;
    const int nk = K >> 6;

    // A x4: m0=(rows0-7,k0-7) m1=(rows8-15,k0-7) m2=(rows0-7,k8-15) m3=(rows8-15,k8-15)
    const uint32_t aOff = (uint32_t)((mW + ((q & 1) << 3) + r) * HPITCHB + ((q >> 1) << 4));
    // B x4: m0=(n0-7,k0-7) m1=(n0-7,k8-15) m2=(n8-15,k0-7) m3=(n8-15,k8-15)
    const uint32_t bOff = (uint32_t)(HASTG + (nW + ((q >> 1) << 3) + r) * HPITCHB + ((q & 1) << 4));

    auto prefetch = [&](int s) {
        const uint32_t aB = sBase + (uint32_t)(s & 1) * HSTAGE;
        const uint32_t bB = aB + HASTG;
        const int k0 = s << 6;
#pragma unroll
        for (int i = 0; i < 3; i++) {           // A: 96 rows x 8 chunks of 16B
            int idx = tid + 256 * i;
            int rr = idx >> 3, ch = idx & 7;
            bool v = (rowBase + rr) < M;
            const __half* src = v ? (A + (size_t)(rowBase + rr) * K + k0 + ch * 8) : A;
            cp16(aB + (uint32_t)(rr * HPITCHB + ch * 16), src, v);
        }
#pragma unroll
        for (int i = 0; i < 4; i++) {           // B: 128 rows x 8 chunks
            int idx = tid + 256 * i;
            int rr = idx >> 3, ch = idx & 7;
            const __half* src = Bt + (size_t)(colBase + rr) * K + k0 + ch * 8;
            cp16(bB + (uint32_t)(rr * HPITCHB + ch * 16), src, true);
        }
        asm volatile("cp.async.commit_group;");
    };

    float acc[3][4][4];
#pragma unroll
    for (int a = 0; a < 3; a++)
#pragma unroll
        for (int b = 0; b < 4; b++)
#pragma unroll
            for (int c = 0; c < 4; c++) acc[a][b][c] = 0.f;

    prefetch(0);

    for (int s = 0; s < nk; s++) {
        if (s + 1 < nk) {
            prefetch(s + 1);
            asm volatile("cp.async.wait_group 1;");
        } else {
            asm volatile("cp.async.wait_group 0;");
        }
        __syncthreads();

        const uint32_t stg = sBase + (uint32_t)(s & 1) * HSTAGE;

#pragma unroll
        for (int kk = 0; kk < 4; kk++) {
            uint32_t af[3][4];
#pragma unroll
            for (int mt = 0; mt < 3; mt++)
                LDSM_X4(af[mt][0], af[mt][1], af[mt][2], af[mt][3],
                        stg + aOff + (uint32_t)(mt * 16 * HPITCHB + kk * 32));
            uint32_t bf[4][2];
#pragma unroll
            for (int np = 0; np < 2; np++)
                LDSM_X4(bf[2 * np][0], bf[2 * np][1], bf[2 * np + 1][0], bf[2 * np + 1][1],
                        stg + bOff + (uint32_t)(np * 16 * HPITCHB + kk * 32));
#pragma unroll
            for (int mt = 0; mt < 3; mt++)
#pragma unroll
                for (int nt = 0; nt < 4; nt++)
                    asm volatile(
                        "mma.sync.aligned.m16n8k16.row.col.f32.f16.f16.f32 "
                        "{%0,%1,%2,%3}, {%4,%5,%6,%7}, {%8,%9}, {%0,%1,%2,%3};"
                        : "+f"(acc[mt][nt][0]), "+f"(acc[mt][nt][1]),
                          "+f"(acc[mt][nt][2]), "+f"(acc[mt][nt][3])
                        : "r"(af[mt][0]), "r"(af[mt][1]), "r"(af[mt][2]), "r"(af[mt][3]),
                          "r"(bf[nt][0]), "r"(bf[nt][1]));
        }
        __syncthreads();
    }

    // epilogue: c0=(g,2t) c1=(g,2t+1) c2=(g+8,2t) c3=(g+8,2t+1)
#pragma unroll
    for (int mt = 0; mt < 3; mt++) {
        const int r0 = rowBase + mW + mt * 16 + g;
#pragma unroll
        for (int half = 0; half < 2; half++) {
            const int rr = r0 + half * 8;
            if (rr >= M) continue;
            const float rs = rowscale ? rowscale[rr] : 1.f;
            const bool masked = (rowscale != nullptr) && (rs == 0.f);
#pragma unroll
            for (int nt = 0; nt < 4; nt++) {
                const int c = colBase + nW + nt * 8 + 2 * t;
                float v0 = acc[mt][nt][half * 2 + 0] * rs + bias[c];
                float v1 = acc[mt][nt][half * 2 + 1] * rs + bias[c + 1];
                if (doRelu) { v0 = fmaxf(v0, 0.f); v1 = fmaxf(v1, 0.f); }
                if (masked) { v0 = 0.f; v1 = 0.f; }
                __half2 hv = __floats2half2_rn(v0, v1);
                *(uint32_t*)(C + (size_t)rr * N + c) = *(uint32_t*)&hv;
            }
        }
    }
}

// ---------------- CSR gather-aggregate: 4 cols/lane (H=128/256) ----------------
__global__ void aggregate_kernel(const __half* __restrict__ t,
                                 const float* __restrict__ wpos,
                                 __half* __restrict__ out, int H, int cbShift)
{
    const int warpGlobal = (blockIdx.x * blockDim.x + threadIdx.x) >> 5;
    const int lane = threadIdx.x & 31;
    const int node = warpGlobal >> cbShift;
    if (node >= NN) return;
    const int cb = warpGlobal & ((1 << cbShift) - 1);
    const int col = cb * 128 + lane * 4;

    const float4 wx = *(const float4*)(wpos + col);
    const float4 wy = *(const float4*)(wpos + H + col);

    const int beg = g_rowptr[node];
    const int end = g_rowptr[node + 1];

    float4 acc = make_float4(0.f, 0.f, 0.f, 0.f);

    for (int b = beg; b < end; b += 32) {
        const int n = min(32, end - b);
        int sj = 0;
        float rxj = 0.f, ryj = 0.f;
        if (b + lane < end) {
            sj = g_esrc[b + lane];
            float2 rr = g_erel[b + lane];
            rxj = rr.x; ryj = rr.y;
        }
#pragma unroll 4
        for (int j = 0; j < n; j++) {
            const int s = __shfl_sync(0xFFFFFFFFu, sj, j);
            const float rx = __shfl_sync(0xFFFFFFFFu, rxj, j);
            const float ry = __shfl_sync(0xFFFFFFFFu, ryj, j);
            uint2 tv = *(const uint2*)(t + (size_t)s * H + col);
            float2 f0 = __half22float2(*reinterpret_cast<__half2*>(&tv.x));
            float2 f1 = __half22float2(*reinterpret_cast<__half2*>(&tv.y));
            acc.x += fmaxf(fmaf(rx, wx.x, fmaf(ry, wy.x, f0.x)), 0.f);
            acc.y += fmaxf(fmaf(rx, wx.y, fmaf(ry, wy.y, f0.y)), 0.f);
            acc.z += fmaxf(fmaf(rx, wx.z, fmaf(ry, wy.z, f1.x)), 0.f);
            acc.w += fmaxf(fmaf(rx, wx.w, fmaf(ry, wy.w, f1.y)), 0.f);
        }
    }
    __half2 h0 = __floats2half2_rn(acc.x, acc.y);
    __half2 h1 = __floats2half2_rn(acc.z, acc.w);
    uint2 o;
    o.x = *(uint32_t*)&h0;
    o.y = *(uint32_t*)&h1;
    *(uint2*)(out + (size_t)node * H + col) = o;
}

// ---------------- CSR gather-aggregate: 8 cols/lane, H=1024 fixed ----------------
__global__ void aggregate8_kernel(const __half* __restrict__ t,
                                  const float* __restrict__ wpos,
                                  __half* __restrict__ out)
{
    const int warpGlobal = (blockIdx.x * blockDim.x + threadIdx.x) >> 5;
    const int lane = threadIdx.x & 31;
    const int node = warpGlobal >> 2;
    if (node >= NN) return;
    const int cb = warpGlobal & 3;
    const int col = cb * 256 + lane * 8;

    const float4 wx0 = *(const float4*)(wpos + col);
    const float4 wx1 = *(const float4*)(wpos + col + 4);
    const float4 wy0 = *(const float4*)(wpos + 1024 + col);
    const float4 wy1 = *(const float4*)(wpos + 1024 + col + 4);

    const int beg = g_rowptr[node];
    const int end = g_rowptr[node + 1];

    float a0 = 0.f, a1 = 0.f, a2 = 0.f, a3 = 0.f;
    float a4 = 0.f, a5 = 0.f, a6 = 0.f, a7 = 0.f;

    for (int b = beg; b < end; b += 32) {
        const int n = min(32, end - b);
        int sj = 0;
        float rxj = 0.f, ryj = 0.f;
        if (b + lane < end) {
            sj = g_esrc[b + lane];
            float2 rr = g_erel[b + lane];
            rxj = rr.x; ryj = rr.y;
        }
#pragma unroll 4
        for (int j = 0; j < n; j++) {
            const int s = __shfl_sync(0xFFFFFFFFu, sj, j);
            const float rx = __shfl_sync(0xFFFFFFFFu, rxj, j);
            const float ry = __shfl_sync(0xFFFFFFFFu, ryj, j);
            uint4 tv = *(const uint4*)(t + (size_t)s * 1024 + col);
            float2 f0 = __half22float2(*reinterpret_cast<__half2*>(&tv.x));
            float2 f1 = __half22float2(*reinterpret_cast<__half2*>(&tv.y));
            float2 f2 = __half22float2(*reinterpret_cast<__half2*>(&tv.z));
            float2 f3 = __half22float2(*reinterpret_cast<__half2*>(&tv.w));
            a0 += fmaxf(fmaf(rx, wx0.x, fmaf(ry, wy0.x, f0.x)), 0.f);
            a1 += fmaxf(fmaf(rx, wx0.y, fmaf(ry, wy0.y, f0.y)), 0.f);
            a2 += fmaxf(fmaf(rx, wx0.z, fmaf(ry, wy0.z, f1.x)), 0.f);
            a3 += fmaxf(fmaf(rx, wx0.w, fmaf(ry, wy0.w, f1.y)), 0.f);
            a4 += fmaxf(fmaf(rx, wx1.x, fmaf(ry, wy1.x, f2.x)), 0.f);
            a5 += fmaxf(fmaf(rx, wx1.y, fmaf(ry, wy1.y, f2.y)), 0.f);
            a6 += fmaxf(fmaf(rx, wx1.z, fmaf(ry, wy1.z, f3.x)), 0.f);
            a7 += fmaxf(fmaf(rx, wx1.w, fmaf(ry, wy1.w, f3.y)), 0.f);
        }
    }
    __half2 h0 = __floats2half2_rn(a0, a1);
    __half2 h1 = __floats2half2_rn(a2, a3);
    __half2 h2 = __floats2half2_rn(a4, a5);
    __half2 h3 = __floats2half2_rn(a6, a7);
    uint4 o;
    o.x = *(uint32_t*)&h0; o.y = *(uint32_t*)&h1;
    o.z = *(uint32_t*)&h2; o.w = *(uint32_t*)&h3;
    *(uint4*)(out + (size_t)node * 1024 + col) = o;
}

// ---------------- final head GEMM (N=4), fp16 A ----------------
__global__ void headN4_kernel(const __half* __restrict__ A, const float* __restrict__ W,
                              const float* __restrict__ b, float* __restrict__ out)
{
    const int warp = (blockIdx.x * blockDim.x + threadIdx.x) >> 5;
    const int lane = threadIdx.x & 31;
    if (warp >= NN) return;
    const __half* ar = A + (size_t)warp * 512;
    float s0 = 0.f, s1 = 0.f, s2 = 0.f, s3 = 0.f;
    for (int k = lane; k < 512; k += 32) {
        const float a = __half2float(ar[k]);
        const float4 w = *(const float4*)(W + k * 4);
        s0 = fmaf(a, w.x, s0); s1 = fmaf(a, w.y, s1);
        s2 = fmaf(a, w.z, s2); s3 = fmaf(a, w.w, s3);
    }
#pragma unroll
    for (int o = 16; o; o >>= 1) {
        s0 += __shfl_down_sync(0xFFFFFFFFu, s0, o);
        s1 += __shfl_down_sync(0xFFFFFFFFu, s1, o);
        s2 += __shfl_down_sync(0xFFFFFFFFu, s2, o);
        s3 += __shfl_down_sync(0xFFFFFFFFu, s3, o);
    }
    if (lane == 0)
        *(float4*)(out + (size_t)warp * 4) =
            make_float4(s0 + b[0], s1 + b[1], s2 + b[2], s3 + b[3]);
}

// ---------------- host helpers ----------------
static inline void run_hgemm(const __half* A, const __half* Bt, const float* bias,
                             const float* rowscale, __half* C, int M, int N, int K, int doRelu)
{
    dim3 grid(N / 128, (M + 95) / 96);
    hgemm_kernel<<<grid, 256, HSMEM_BYTES>>>(A, Bt, bias, rowscale, C, M, N, K, doRelu);
}

static inline void run_agg(const __half* t, const float* wpos, __half* s, int H, int cbShift)
{
    const long long threads = ((long long)NN << cbShift) * 32;
    aggregate_kernel<<<(unsigned)((threads + 255) / 256), 256>>>(t, wpos, s, H, cbShift);
}

static inline void run_agg8(const __half* t, const float* wpos, __half* s)
{
    const long long threads = (long long)NN * 4 * 32;
    aggregate8_kernel<<<(unsigned)((threads + 255) / 256), 256>>>(t, wpos, s);
}

static inline void run_trc_s(cudaStream_t st, const float* src, __half* dst,
                             int Kreal, int N, int Kp)
{
    trconv_kernel<<<dim3((N + 31) / 32, (Kreal + 31) / 32), dim3(32, 8), 0, st>>>(
        src, dst, Kreal, N, Kp);
}

extern "C" void kernel_launch(void* const* d_in, const int* in_sizes, int n_in,
                              void* d_out, int out_size)
{
    const float* h    = (const float*)d_in[0];
    const float* pos  = (const float*)d_in[1];
    const void*  eidx = d_in[2];

    const float* l1_w1 = (const float*)d_in[3];
    const float* l1_b1 = (const float*)d_in[4];
    const float* l1_w2 = (const float*)d_in[5];
    const float* l1_b2 = (const float*)d_in[6];
    const float* l2_w1 = (const float*)d_in[7];
    const float* l2_b1 = (const float*)d_in[8];
    const float* l2_w2 = (const float*)d_in[9];
    const float* l2_b2 = (const float*)d_in[10];
    const float* l3_w1 = (const float*)d_in[11];
    const float* l3_b1 = (const float*)d_in[12];
    const float* l3_w2 = (const float*)d_in[13];
    const float* l3_b2 = (const float*)d_in[14];
    const float* l4_w1 = (const float*)d_in[15];
    const float* l4_b1 = (const float*)d_in[16];
    const float* l4_w2 = (const float*)d_in[17];
    const float* l4_b2 = (const float*)d_in[18];
    const float* hd_w1 = (const float*)d_in[19];
    const float* hd_b1 = (const float*)d_in[20];
    const float* hd_w2 = (const float*)d_in[21];
    const float* hd_b2 = (const float*)d_in[22];
    const float* hd_w3 = (const float*)d_in[23];
    const float* hd_b3 = (const float*)d_in[24];

    __half *hA, *hB, *hC, *h16, *w16;
    float* inv;
    cudaGetSymbolAddress((void**)&hA, g_hA);
    cudaGetSymbolAddress((void**)&hB, g_hB);
    cudaGetSymbolAddress((void**)&hC, g_hC);
    cudaGetSymbolAddress((void**)&h16, g_h16);
    cudaGetSymbolAddress((void**)&w16, g_w16);
    cudaGetSymbolAddress((void**)&inv, g_inv);

    cudaFuncSetAttribute(hgemm_kernel,
                         cudaFuncAttributeMaxDynamicSharedMemorySize, HSMEM_BYTES);

    // side stream + events (created once; reused across calls)
    static cudaStream_t s1 = nullptr;
    static cudaEvent_t evF = nullptr, evCSR = nullptr, evW = nullptr;
    if (s1 == nullptr) {
        cudaStreamCreateWithFlags(&s1, cudaStreamNonBlocking);
        cudaEventCreateWithFlags(&evF, cudaEventDisableTiming);
        cudaEventCreateWithFlags(&evCSR, cudaEventDisableTiming);
        cudaEventCreateWithFlags(&evW, cudaEventDisableTiming);
    }

    // fork s1 off the main stream
    cudaEventRecord(evF, 0);
    cudaStreamWaitEvent(s1, evF, 0);

    // s1: CSR build
    detect_idx_kernel<<<1, 32, 0, s1>>>((const int*)d_in[2]);
    zero2_int_kernel<<<(NN + 255) / 256, 256, 0, s1>>>();
    count_kernel<<<(NE + 255) / 256, 256, 0, s1>>>(eidx);
    scan_kernel<<<1, 1024, 0, s1>>>();
    fill_kernel<<<(NE + 255) / 256, 256, 0, s1>>>(eidx, pos);
    make_inv_kernel<<<(NN + 255) / 256, 256, 0, s1>>>();
    cudaEventRecord(evCSR, s1);

    // s1: weight transposes for layers 2..head
    run_trc_s(s1, l2_w1, w16 + O_L2W1, 128, 256, 128);
    run_trc_s(s1, l2_w2, w16 + O_L2W2, 256, 256, 256);
    run_trc_s(s1, l3_w1, w16 + O_L3W1, 256, 1024, 256);
    run_trc_s(s1, l3_w2, w16 + O_L3W2, 1024, 1024, 1024);
    run_trc_s(s1, l4_w1, w16 + O_L4W1, 1024, 1024, 1024);
    run_trc_s(s1, l4_w2, w16 + O_L4W2, 1024, 1024, 1024);
    run_trc_s(s1, hd_w1, w16 + O_HDW1, 1024, 1024, 1024);
    run_trc_s(s1, hd_w2, w16 + O_HDW2, 1024, 512, 1024);
    cudaEventRecord(evW, s1);

    // main stream: layer-1 prep + GEMM1 (overlaps with s1)
    convh_kernel<<<(NN * 16 + 255) / 256, 256>>>(h);
    run_trc_s(0, l1_w1, w16 + O_L1W1, 16, 128, 64);
    run_trc_s(0, l1_w2, w16 + O_L1W2, 128, 128, 128);
    run_hgemm(h16, w16 + O_L1W1, l1_b1, nullptr, hB, NN, 128, 64, 0);

    // join CSR before aggregation
    cudaStreamWaitEvent(0, evCSR, 0);
    run_agg(hB, l1_w1 + (size_t)16 * 128, hC, 128, 0);
    run_hgemm(hC, w16 + O_L1W2, l1_b2, inv, hA, NN, 128, 128, 1);

    // join weights before layer 2
    cudaStreamWaitEvent(0, evW, 0);

    // --- layer 2: 128 -> 256 -> 256 ---
    run_hgemm(hA, w16 + O_L2W1, l2_b1, nullptr, hB, NN, 256, 128, 0);
    run_agg(hB, l2_w1 + (size_t)128 * 256, hC, 256, 1);
    run_hgemm(hC, w16 + O_L2W2, l2_b2, inv, hA, NN, 256, 256, 1);

    // --- layer 3: 256 -> 1024 -> 1024 ---
    run_hgemm(hA, w16 + O_L3W1, l3_b1, nullptr, hB, NN, 1024, 256, 0);
    run_agg8(hB, l3_w1 + (size_t)256 * 1024, hC);
    run_hgemm(hC, w16 + O_L3W2, l3_b2, inv, hA, NN, 1024, 1024, 1);

    // --- layer 4: 1024 -> 1024 -> 1024 ---
    run_hgemm(hA, w16 + O_L4W1, l4_b1, nullptr, hB, NN, 1024, 1024, 0);
    run_agg8(hB, l4_w1 + (size_t)1024 * 1024, hC);
    run_hgemm(hC, w16 + O_L4W2, l4_b2, inv, hA, NN, 1024, 1024, 1);

    // --- head MLP ---
    run_hgemm(hA, w16 + O_HDW1, hd_b1, nullptr, hB, NN, 1024, 1024, 1);
    run_hgemm(hB, w16 + O_HDW2, hd_b2, nullptr, hC, NN, 512, 1024, 1);
    headN4_kernel<<<(NN * 32 + 255) / 256, 256>>>(hC, hd_w3, hd_b3, (float*)d_out);
}

// round 12
// speedup vs baseline: 1.0201x; 1.0201x over previous
#include <cuda_runtime.h>
#include <cuda_fp16.h>
#include <stdint.h>

#define NN 20000
#define NE 320000

// ---------------- static scratch (BSS zero-init gives free zero padding) ----------------
__device__ __half g_hA[(size_t)NN * 1024];
__device__ __half g_hB[(size_t)NN * 1024];
__device__ __half g_hC[(size_t)NN * 1024];
__device__ __half g_h16[(size_t)NN * 64];      // h padded 16 -> 64 cols
__device__ __half g_w16[5128192];              // transposed fp16 weights
__device__ float g_inv[NN];
__device__ int   g_cnti[NN];
__device__ int   g_fill[NN];
__device__ int   g_rowptr[NN + 1];
__device__ int   g_esrc[NE];
__device__ float2 g_erel[NE];
__device__ int   g_idx64;

// transposed fp16 weight offsets (halves). [Np][Kp] layouts.
#define O_L1W1 0          // 256 x 64   (real 128 x 16)
#define O_L1W2 16384      // 256 x 128
#define O_L2W1 49152      // 256 x 128
#define O_L2W2 81920      // 256 x 256
#define O_L3W1 147456     // 1024 x 256
#define O_L3W2 409600     // 1024 x 1024
#define O_L4W1 1458176
#define O_L4W2 2506752
#define O_HDW1 3555328
#define O_HDW2 4603904    // 512 x 1024

__device__ __forceinline__ void cp16(uint32_t dst, const void* src, bool v) {
    if (v)
        asm volatile("cp.async.cg.shared.global [%0], [%1], 16;" :: "r"(dst), "l"(src));
    else
        asm volatile("cp.async.cg.shared.global [%0], [%1], 16, 0;" :: "r"(dst), "l"(src));
}

#define LDSM_X4(r0, r1, r2, r3, addr) \
    asm volatile("ldmatrix.sync.aligned.m8n8.x4.shared.b16 {%0,%1,%2,%3}, [%4];" \
                 : "=r"(r0), "=r"(r1), "=r"(r2), "=r"(r3) : "r"(addr))

// ---------------- setup kernels ----------------
__global__ void detect_idx_kernel(const int* e) {
    if (threadIdx.x == 0 && blockIdx.x == 0) {
        int is64 = 1;
        for (int k = 0; k < 128; k++) {
            if (e[2 * k + 1] != 0) { is64 = 0; break; }
        }
        g_idx64 = is64;
    }
}

__global__ void zero2_int_kernel() {
    int i = blockIdx.x * blockDim.x + threadIdx.x;
    if (i < NN) { g_cnti[i] = 0; g_fill[i] = 0; }
}

__global__ void count_kernel(const void* eidx) {
    int e = blockIdx.x * blockDim.x + threadIdx.x;
    if (e >= NE) return;
    int d;
    if (g_idx64) d = (int)((const long long*)eidx)[(long long)NE + e];
    else         d = ((const int*)eidx)[NE + e];
    atomicAdd(&g_cnti[d], 1);
}

__global__ void scan_kernel() {
    __shared__ int part[1024];
    const int t = threadIdx.x;
    const int CH = 20;
    const int base = t * CH;
    int s = 0;
    for (int i = 0; i < CH; i++) {
        int idx = base + i;
        if (idx < NN) s += g_cnti[idx];
    }
    part[t] = s;
    __syncthreads();
    for (int off = 1; off < 1024; off <<= 1) {
        int v = 0;
        if (t >= off) v = part[t - off];
        __syncthreads();
        part[t] += v;
        __syncthreads();
    }
    int run = (t == 0) ? 0 : part[t - 1];
    for (int i = 0; i < CH; i++) {
        int idx = base + i;
        if (idx < NN) { g_rowptr[idx] = run; run += g_cnti[idx]; }
    }
    if (t == 1023) g_rowptr[NN] = part[1023];
}

__global__ void fill_kernel(const void* eidx, const float* __restrict__ pos) {
    int e = blockIdx.x * blockDim.x + threadIdx.x;
    if (e >= NE) return;
    int s, d;
    if (g_idx64) {
        s = (int)((const long long*)eidx)[e];
        d = (int)((const long long*)eidx)[(long long)NE + e];
    } else {
        s = ((const int*)eidx)[e];
        d = ((const int*)eidx)[NE + e];
    }
    int p = g_rowptr[d] + atomicAdd(&g_fill[d], 1);
    g_esrc[p] = s;
    g_erel[p] = make_float2(pos[2 * s] - pos[2 * d], pos[2 * s + 1] - pos[2 * d + 1]);
}

__global__ void make_inv_kernel() {
    int i = blockIdx.x * blockDim.x + threadIdx.x;
    if (i < NN) {
        int c = g_rowptr[i + 1] - g_rowptr[i];
        g_inv[i] = (c > 0) ? (1.f / (float)c) : 0.f;
    }
}

// W[K][N] fp32 -> WT[N][Kp] fp16 (zero-fill k in [Kreal, Kp))
__global__ void trconv_kernel(const float* __restrict__ src, __half* __restrict__ dst,
                              int Kreal, int N, int Kp)
{
    __shared__ float tile[32][33];
    const int bx = blockIdx.x * 32;  // n
    const int by = blockIdx.y * 32;  // k
    const int x = threadIdx.x, y = threadIdx.y;
    for (int i = 0; i < 32; i += 8) {
        int k = by + y + i, n = bx + x;
        tile[y + i][x] = (k < Kreal && n < N) ? src[(size_t)k * N + n] : 0.f;
    }
    __syncthreads();
    for (int i = 0; i < 32; i += 8) {
        int n = bx + y + i, k = by + x;
        if (n < N && k < Kp) dst[(size_t)n * Kp + k] = __float2half_rn(tile[x][y + i]);
    }
}

__global__ void convh_kernel(const float* __restrict__ h) {
    int idx = blockIdx.x * blockDim.x + threadIdx.x;
    if (idx >= NN * 16) return;
    int r = idx >> 4, c = idx & 15;
    g_h16[(size_t)r * 64 + c] = __float2half_rn(h[idx]);
}

// ---------------- fp16 MMA GEMM: 128x128 tile, BK=64, 3-stage, 2 CTAs/SM ----------------
#define HPITCHB 144                     // bytes per smem row (72 halves)
#define HASTG  (128 * HPITCHB)          // 18432
#define HBSTG  (128 * HPITCHB)          // 18432
#define HSTAGE (HASTG + HBSTG)          // 36864
#define HSMEM_BYTES (3 * HSTAGE)        // 110592 per CTA -> 2 CTAs/SM (221KB/SM)

__global__ void __launch_bounds__(256, 2)
hgemm_kernel(const __half* __restrict__ A, const __half* __restrict__ Bt,
             const float* __restrict__ bias, const float* __restrict__ rowscale,
             __half* __restrict__ C, int M, int N, int K, int doRelu)
{
    extern __shared__ char smemc[];
    const uint32_t sBase = (uint32_t)__cvta_generic_to_shared(smemc);

    const int tid = threadIdx.x;
    const int wid = tid >> 5, lane = tid & 31;
    const int wr = wid >> 2, wc = wid & 3;
    const int mW = wr * 64, nW = wc * 32;
    const int g = lane >> 2, t = lane & 3;
    const int q = lane >> 3, r = lane & 7;
    const int rowBase = blockIdx.y * 128;
    const int colBase = blockIdx.x * 128;
    const int nk = K >> 6;

    // A x4: m0=(rows0-7,k0-7) m1=(rows8-15,k0-7) m2=(rows0-7,k8-15) m3=(rows8-15,k8-15)
    const uint32_t aOff = (uint32_t)((mW + ((q & 1) << 3) + r) * HPITCHB + ((q >> 1) << 4));
    // B x4: m0=(n0-7,k0-7) m1=(n0-7,k8-15) m2=(n8-15,k0-7) m3=(n8-15,k8-15)
    const uint32_t bOff = (uint32_t)(HASTG + (nW + ((q >> 1) << 3) + r) * HPITCHB + ((q & 1) << 4));

    auto prefetch = [&](int s) {
        const uint32_t aB = sBase + (uint32_t)(s % 3) * HSTAGE;
        const uint32_t bB = aB + HASTG;
        const int k0 = s << 6;
#pragma unroll
        for (int i = 0; i < 4; i++) {           // A: 128 rows x 8 chunks of 16B
            int idx = tid + 256 * i;
            int rr = idx >> 3, ch = idx & 7;
            bool v = (rowBase + rr) < M;
            const __half* src = v ? (A + (size_t)(rowBase + rr) * K + k0 + ch * 8) : A;
            cp16(aB + (uint32_t)(rr * HPITCHB + ch * 16), src, v);
        }
#pragma unroll
        for (int i = 0; i < 4; i++) {           // B: 128 rows x 8 chunks
            int idx = tid + 256 * i;
            int rr = idx >> 3, ch = idx & 7;
            const __half* src = Bt + (size_t)(colBase + rr) * K + k0 + ch * 8;
            cp16(bB + (uint32_t)(rr * HPITCHB + ch * 16), src, true);
        }
        asm volatile("cp.async.commit_group;");
    };

    float acc[4][4][4];
#pragma unroll
    for (int a = 0; a < 4; a++)
#pragma unroll
        for (int b = 0; b < 4; b++)
#pragma unroll
            for (int c = 0; c < 4; c++) acc[a][b][c] = 0.f;

    prefetch(0);
    if (1 < nk) prefetch(1);

    for (int s = 0; s < nk; s++) {
        if (s + 2 < nk) {
            prefetch(s + 2);
            asm volatile("cp.async.wait_group 2;");
        } else if (s + 1 < nk) {
            asm volatile("cp.async.wait_group 1;");
        } else {
            asm volatile("cp.async.wait_group 0;");
        }
        __syncthreads();

        const uint32_t stg = sBase + (uint32_t)(s % 3) * HSTAGE;

#pragma unroll
        for (int kk = 0; kk < 4; kk++) {
            uint32_t af[4][4];
#pragma unroll
            for (int mt = 0; mt < 4; mt++)
                LDSM_X4(af[mt][0], af[mt][1], af[mt][2], af[mt][3],
                        stg + aOff + (uint32_t)(mt * 16 * HPITCHB + kk * 32));
            uint32_t bf[4][2];
#pragma unroll
            for (int np = 0; np < 2; np++)
                LDSM_X4(bf[2 * np][0], bf[2 * np][1], bf[2 * np + 1][0], bf[2 * np + 1][1],
                        stg + bOff + (uint32_t)(np * 16 * HPITCHB + kk * 32));
#pragma unroll
            for (int mt = 0; mt < 4; mt++)
#pragma unroll
                for (int nt = 0; nt < 4; nt++)
                    asm volatile(
                        "mma.sync.aligned.m16n8k16.row.col.f32.f16.f16.f32 "
                        "{%0,%1,%2,%3}, {%4,%5,%6,%7}, {%8,%9}, {%0,%1,%2,%3};"
                        : "+f"(acc[mt][nt][0]), "+f"(acc[mt][nt][1]),
                          "+f"(acc[mt][nt][2]), "+f"(acc[mt][nt][3])
                        : "r"(af[mt][0]), "r"(af[mt][1]), "r"(af[mt][2]), "r"(af[mt][3]),
                          "r"(bf[nt][0]), "r"(bf[nt][1]));
        }
        __syncthreads();
    }

    // epilogue: c0=(g,2t) c1=(g,2t+1) c2=(g+8,2t) c3=(g+8,2t+1)
#pragma unroll
    for (int mt = 0; mt < 4; mt++) {
        const int r0 = rowBase + mW + mt * 16 + g;
#pragma unroll
        for (int half = 0; half < 2; half++) {
            const int rr = r0 + half * 8;
            if (rr >= M) continue;
            const float rs = rowscale ? rowscale[rr] : 1.f;
            const bool masked = (rowscale != nullptr) && (rs == 0.f);
#pragma unroll
            for (int nt = 0; nt < 4; nt++) {
                const int c = colBase + nW + nt * 8 + 2 * t;
                float v0 = acc[mt][nt][half * 2 + 0] * rs + bias[c];
                float v1 = acc[mt][nt][half * 2 + 1] * rs + bias[c + 1];
                if (doRelu) { v0 = fmaxf(v0, 0.f); v1 = fmaxf(v1, 0.f); }
                if (masked) { v0 = 0.f; v1 = 0.f; }
                __half2 hv = __floats2half2_rn(v0, v1);
                *(uint32_t*)(C + (size_t)rr * N + c) = *(uint32_t*)&hv;
            }
        }
    }
}

// ---------------- CSR gather-aggregate: 4 cols/lane (H=128/256) ----------------
__global__ void aggregate_kernel(const __half* __restrict__ t,
                                 const float* __restrict__ wpos,
                                 __half* __restrict__ out, int H, int cbShift)
{
    const int warpGlobal = (blockIdx.x * blockDim.x + threadIdx.x) >> 5;
    const int lane = threadIdx.x & 31;
    const int node = warpGlobal >> cbShift;
    if (node >= NN) return;
    const int cb = warpGlobal & ((1 << cbShift) - 1);
    const int col = cb * 128 + lane * 4;

    const float4 wx = *(const float4*)(wpos + col);
    const float4 wy = *(const float4*)(wpos + H + col);

    const int beg = g_rowptr[node];
    const int end = g_rowptr[node + 1];

    float4 acc = make_float4(0.f, 0.f, 0.f, 0.f);

    for (int b = beg; b < end; b += 32) {
        const int n = min(32, end - b);
        int sj = 0;
        float rxj = 0.f, ryj = 0.f;
        if (b + lane < end) {
            sj = g_esrc[b + lane];
            float2 rr = g_erel[b + lane];
            rxj = rr.x; ryj = rr.y;
        }
#pragma unroll 4
        for (int j = 0; j < n; j++) {
            const int s = __shfl_sync(0xFFFFFFFFu, sj, j);
            const float rx = __shfl_sync(0xFFFFFFFFu, rxj, j);
            const float ry = __shfl_sync(0xFFFFFFFFu, ryj, j);
            uint2 tv = *(const uint2*)(t + (size_t)s * H + col);
            float2 f0 = __half22float2(*reinterpret_cast<__half2*>(&tv.x));
            float2 f1 = __half22float2(*reinterpret_cast<__half2*>(&tv.y));
            acc.x += fmaxf(fmaf(rx, wx.x, fmaf(ry, wy.x, f0.x)), 0.f);
            acc.y += fmaxf(fmaf(rx, wx.y, fmaf(ry, wy.y, f0.y)), 0.f);
            acc.z += fmaxf(fmaf(rx, wx.z, fmaf(ry, wy.z, f1.x)), 0.f);
            acc.w += fmaxf(fmaf(rx, wx.w, fmaf(ry, wy.w, f1.y)), 0.f);
        }
    }
    __half2 h0 = __floats2half2_rn(acc.x, acc.y);
    __half2 h1 = __floats2half2_rn(acc.z, acc.w);
    uint2 o;
    o.x = *(uint32_t*)&h0;
    o.y = *(uint32_t*)&h1;
    *(uint2*)(out + (size_t)node * H + col) = o;
}

// ---------------- CSR gather-aggregate: 8 cols/lane, H=1024 fixed ----------------
__global__ void aggregate8_kernel(const __half* __restrict__ t,
                                  const float* __restrict__ wpos,
                                  __half* __restrict__ out)
{
    const int warpGlobal = (blockIdx.x * blockDim.x + threadIdx.x) >> 5;
    const int lane = threadIdx.x & 31;
    const int node = warpGlobal >> 2;
    if (node >= NN) return;
    const int cb = warpGlobal & 3;
    const int col = cb * 256 + lane * 8;

    const float4 wx0 = *(const float4*)(wpos + col);
    const float4 wx1 = *(const float4*)(wpos + col + 4);
    const float4 wy0 = *(const float4*)(wpos + 1024 + col);
    const float4 wy1 = *(const float4*)(wpos + 1024 + col + 4);

    const int beg = g_rowptr[node];
    const int end = g_rowptr[node + 1];

    float a0 = 0.f, a1 = 0.f, a2 = 0.f, a3 = 0.f;
    float a4 = 0.f, a5 = 0.f, a6 = 0.f, a7 = 0.f;

    for (int b = beg; b < end; b += 32) {
        const int n = min(32, end - b);
        int sj = 0;
        float rxj = 0.f, ryj = 0.f;
        if (b + lane < end) {
            sj = g_esrc[b + lane];
            float2 rr = g_erel[b + lane];
            rxj = rr.x; ryj = rr.y;
        }
#pragma unroll 4
        for (int j = 0; j < n; j++) {
            const int s = __shfl_sync(0xFFFFFFFFu, sj, j);
            const float rx = __shfl_sync(0xFFFFFFFFu, rxj, j);
            const float ry = __shfl_sync(0xFFFFFFFFu, ryj, j);
            uint4 tv = *(const uint4*)(t + (size_t)s * 1024 + col);
            float2 f0 = __half22float2(*reinterpret_cast<__half2*>(&tv.x));
            float2 f1 = __half22float2(*reinterpret_cast<__half2*>(&tv.y));
            float2 f2 = __half22float2(*reinterpret_cast<__half2*>(&tv.z));
            float2 f3 = __half22float2(*reinterpret_cast<__half2*>(&tv.w));
            a0 += fmaxf(fmaf(rx, wx0.x, fmaf(ry, wy0.x, f0.x)), 0.f);
            a1 += fmaxf(fmaf(rx, wx0.y, fmaf(ry, wy0.y, f0.y)), 0.f);
            a2 += fmaxf(fmaf(rx, wx0.z, fmaf(ry, wy0.z, f1.x)), 0.f);
            a3 += fmaxf(fmaf(rx, wx0.w, fmaf(ry, wy0.w, f1.y)), 0.f);
            a4 += fmaxf(fmaf(rx, wx1.x, fmaf(ry, wy1.x, f2.x)), 0.f);
            a5 += fmaxf(fmaf(rx, wx1.y, fmaf(ry, wy1.y, f2.y)), 0.f);
            a6 += fmaxf(fmaf(rx, wx1.z, fmaf(ry, wy1.z, f3.x)), 0.f);
            a7 += fmaxf(fmaf(rx, wx1.w, fmaf(ry, wy1.w, f3.y)), 0.f);
        }
    }
    __half2 h0 = __floats2half2_rn(a0, a1);
    __half2 h1 = __floats2half2_rn(a2, a3);
    __half2 h2 = __floats2half2_rn(a4, a5);
    __half2 h3 = __floats2half2_rn(a6, a7);
    uint4 o;
    o.x = *(uint32_t*)&h0; o.y = *(uint32_t*)&h1;
    o.z = *(uint32_t*)&h2; o.w = *(uint32_t*)&h3;
    *(uint4*)(out + (size_t)node * 1024 + col) = o;
}

// ---------------- final head GEMM (N=4), fp16 A ----------------
__global__ void headN4_kernel(const __half* __restrict__ A, const float* __restrict__ W,
                              const float* __restrict__ b, float* __restrict__ out)
{
    const int warp = (blockIdx.x * blockDim.x + threadIdx.x) >> 5;
    const int lane = threadIdx.x & 31;
    if (warp >= NN) return;
    const __half* ar = A + (size_t)warp * 512;
    float s0 = 0.f, s1 = 0.f, s2 = 0.f, s3 = 0.f;
    for (int k = lane; k < 512; k += 32) {
        const float a = __half2float(ar[k]);
        const float4 w = *(const float4*)(W + k * 4);
        s0 = fmaf(a, w.x, s0); s1 = fmaf(a, w.y, s1);
        s2 = fmaf(a, w.z, s2); s3 = fmaf(a, w.w, s3);
    }
#pragma unroll
    for (int o = 16; o; o >>= 1) {
        s0 += __shfl_down_sync(0xFFFFFFFFu, s0, o);
        s1 += __shfl_down_sync(0xFFFFFFFFu, s1, o);
        s2 += __shfl_down_sync(0xFFFFFFFFu, s2, o);
        s3 += __shfl_down_sync(0xFFFFFFFFu, s3, o);
    }
    if (lane == 0)
        *(float4*)(out + (size_t)warp * 4) =
            make_float4(s0 + b[0], s1 + b[1], s2 + b[2], s3 + b[3]);
}

// ---------------- host helpers ----------------
static inline void run_hgemm(const __half* A, const __half* Bt, const float* bias,
                             const float* rowscale, __half* C, int M, int N, int K, int doRelu)
{
    dim3 grid(N / 128, (M + 127) / 128);
    hgemm_kernel<<<grid, 256, HSMEM_BYTES>>>(A, Bt, bias, rowscale, C, M, N, K, doRelu);
}

static inline void run_agg(const __half* t, const float* wpos, __half* s, int H, int cbShift)
{
    const long long threads = ((long long)NN << cbShift) * 32;
    aggregate_kernel<<<(unsigned)((threads + 255) / 256), 256>>>(t, wpos, s, H, cbShift);
}

static inline void run_agg8(const __half* t, const float* wpos, __half* s)
{
    const long long threads = (long long)NN * 4 * 32;
    aggregate8_kernel<<<(unsigned)((threads + 255) / 256), 256>>>(t, wpos, s);
}

static inline void run_trc_s(cudaStream_t st, const float* src, __half* dst,
                             int Kreal, int N, int Kp)
{
    trconv_kernel<<<dim3((N + 31) / 32, (Kreal + 31) / 32), dim3(32, 8), 0, st>>>(
        src, dst, Kreal, N, Kp);
}

extern "C" void kernel_launch(void* const* d_in, const int* in_sizes, int n_in,
                              void* d_out, int out_size)
{
    const float* h    = (const float*)d_in[0];
    const float* pos  = (const float*)d_in[1];
    const void*  eidx = d_in[2];

    const float* l1_w1 = (const float*)d_in[3];
    const float* l1_b1 = (const float*)d_in[4];
    const float* l1_w2 = (const float*)d_in[5];
    const float* l1_b2 = (const float*)d_in[6];
    const float* l2_w1 = (const float*)d_in[7];
    const float* l2_b1 = (const float*)d_in[8];
    const float* l2_w2 = (const float*)d_in[9];
    const float* l2_b2 = (const float*)d_in[10];
    const float* l3_w1 = (const float*)d_in[11];
    const float* l3_b1 = (const float*)d_in[12];
    const float* l3_w2 = (const float*)d_in[13];
    const float* l3_b2 = (const float*)d_in[14];
    const float* l4_w1 = (const float*)d_in[15];
    const float* l4_b1 = (const float*)d_in[16];
    const float* l4_w2 = (const float*)d_in[17];
    const float* l4_b2 = (const float*)d_in[18];
    const float* hd_w1 = (const float*)d_in[19];
    const float* hd_b1 = (const float*)d_in[20];
    const float* hd_w2 = (const float*)d_in[21];
    const float* hd_b2 = (const float*)d_in[22];
    const float* hd_w3 = (const float*)d_in[23];
    const float* hd_b3 = (const float*)d_in[24];

    __half *hA, *hB, *hC, *h16, *w16;
    float* inv;
    cudaGetSymbolAddress((void**)&hA, g_hA);
    cudaGetSymbolAddress((void**)&hB, g_hB);
    cudaGetSymbolAddress((void**)&hC, g_hC);
    cudaGetSymbolAddress((void**)&h16, g_h16);
    cudaGetSymbolAddress((void**)&w16, g_w16);
    cudaGetSymbolAddress((void**)&inv, g_inv);

    cudaFuncSetAttribute(hgemm_kernel,
                         cudaFuncAttributeMaxDynamicSharedMemorySize, HSMEM_BYTES);

    // side stream + events (created once; reused across calls)
    static cudaStream_t s1 = nullptr;
    static cudaEvent_t evF = nullptr, evCSR = nullptr, evW = nullptr;
    if (s1 == nullptr) {
        cudaStreamCreateWithFlags(&s1, cudaStreamNonBlocking);
        cudaEventCreateWithFlags(&evF, cudaEventDisableTiming);
        cudaEventCreateWithFlags(&evCSR, cudaEventDisableTiming);
        cudaEventCreateWithFlags(&evW, cudaEventDisableTiming);
    }

    // fork s1 off the main stream
    cudaEventRecord(evF, 0);
    cudaStreamWaitEvent(s1, evF, 0);

    // s1: CSR build
    detect_idx_kernel<<<1, 32, 0, s1>>>((const int*)d_in[2]);
    zero2_int_kernel<<<(NN + 255) / 256, 256, 0, s1>>>();
    count_kernel<<<(NE + 255) / 256, 256, 0, s1>>>(eidx);
    scan_kernel<<<1, 1024, 0, s1>>>();
    fill_kernel<<<(NE + 255) / 256, 256, 0, s1>>>(eidx, pos);
    make_inv_kernel<<<(NN + 255) / 256, 256, 0, s1>>>();
    cudaEventRecord(evCSR, s1);

    // s1: weight transposes for layers 2..head
    run_trc_s(s1, l2_w1, w16 + O_L2W1, 128, 256, 128);
    run_trc_s(s1, l2_w2, w16 + O_L2W2, 256, 256, 256);
    run_trc_s(s1, l3_w1, w16 + O_L3W1, 256, 1024, 256);
    run_trc_s(s1, l3_w2, w16 + O_L3W2, 1024, 1024, 1024);
    run_trc_s(s1, l4_w1, w16 + O_L4W1, 1024, 1024, 1024);
    run_trc_s(s1, l4_w2, w16 + O_L4W2, 1024, 1024, 1024);
    run_trc_s(s1, hd_w1, w16 + O_HDW1, 1024, 1024, 1024);
    run_trc_s(s1, hd_w2, w16 + O_HDW2, 1024, 512, 1024);
    cudaEventRecord(evW, s1);

    // main stream: layer-1 prep + GEMM1 (overlaps with s1)
    convh_kernel<<<(NN * 16 + 255) / 256, 256>>>(h);
    run_trc_s(0, l1_w1, w16 + O_L1W1, 16, 128, 64);
    run_trc_s(0, l1_w2, w16 + O_L1W2, 128, 128, 128);
    run_hgemm(h16, w16 + O_L1W1, l1_b1, nullptr, hB, NN, 128, 64, 0);

    // join CSR before aggregation
    cudaStreamWaitEvent(0, evCSR, 0);
    run_agg(hB, l1_w1 + (size_t)16 * 128, hC, 128, 0);
    run_hgemm(hC, w16 + O_L1W2, l1_b2, inv, hA, NN, 128, 128, 1);

    // join weights before layer 2
    cudaStreamWaitEvent(0, evW, 0);

    // --- layer 2: 128 -> 256 -> 256 ---
    run_hgemm(hA, w16 + O_L2W1, l2_b1, nullptr, hB, NN, 256, 128, 0);
    run_agg(hB, l2_w1 + (size_t)128 * 256, hC, 256, 1);
    run_hgemm(hC, w16 + O_L2W2, l2_b2, inv, hA, NN, 256, 256, 1);

    // --- layer 3: 256 -> 1024 -> 1024 ---
    run_hgemm(hA, w16 + O_L3W1, l3_b1, nullptr, hB, NN, 1024, 256, 0);
    run_agg8(hB, l3_w1 + (size_t)256 * 1024, hC);
    run_hgemm(hC, w16 + O_L3W2, l3_b2, inv, hA, NN, 1024, 1024, 1);

    // --- layer 4: 1024 -> 1024 -> 1024 ---
    run_hgemm(hA, w16 + O_L4W1, l4_b1, nullptr, hB, NN, 1024, 1024, 0);
    run_agg8(hB, l4_w1 + (size_t)1024 * 1024, hC);
    run_hgemm(hC, w16 + O_L4W2, l4_b2, inv, hA, NN, 1024, 1024, 1);

    // --- head MLP ---
    run_hgemm(hA, w16 + O_HDW1, hd_b1, nullptr, hB, NN, 1024, 1024, 1);
    run_hgemm(hB, w16 + O_HDW2, hd_b2, nullptr, hC, NN, 512, 1024, 1);
    headN4_kernel<<<(NN * 32 + 255) / 256, 256>>>(hC, hd_w3, hd_b3, (float*)d_out);
}

// round 14
// speedup vs baseline: 1.0323x; 1.0120x over previous
#include <cuda_runtime.h>
#include <cuda_fp16.h>
#include <stdint.h>

#define NN 20000
#define NE 320000

// ---------------- static scratch (BSS zero-init gives free zero padding) ----------------
__device__ __half g_hA[(size_t)NN * 1024];
__device__ __half g_hB[(size_t)NN * 1024];
__device__ __half g_hC[(size_t)NN * 1024];
__device__ __half g_h16[(size_t)NN * 64];      // h padded 16 -> 64 cols
__device__ __half g_w16[5128192];              // transposed fp16 weights
__device__ float g_inv[NN];
__device__ int   g_cnti[NN];
__device__ int   g_fill[NN];
__device__ int   g_rowptr[NN + 1];
__device__ int   g_esrc[NE];
__device__ float2 g_erel[NE];
__device__ int   g_idx64;

// transposed fp16 weight offsets (halves). [Np][Kp] layouts.
#define O_L1W1 0          // 256 x 64   (real 128 x 16)
#define O_L1W2 16384      // 256 x 128
#define O_L2W1 49152      // 256 x 128
#define O_L2W2 81920      // 256 x 256
#define O_L3W1 147456     // 1024 x 256
#define O_L3W2 409600     // 1024 x 1024
#define O_L4W1 1458176
#define O_L4W2 2506752
#define O_HDW1 3555328
#define O_HDW2 4603904    // 512 x 1024

__device__ __forceinline__ void cp16(uint32_t dst, const void* src, bool v) {
    if (v)
        asm volatile("cp.async.cg.shared.global [%0], [%1], 16;" :: "r"(dst), "l"(src));
    else
        asm volatile("cp.async.cg.shared.global [%0], [%1], 16, 0;" :: "r"(dst), "l"(src));
}

#define LDSM_X4(r0, r1, r2, r3, addr) \
    asm volatile("ldmatrix.sync.aligned.m8n8.x4.shared.b16 {%0,%1,%2,%3}, [%4];" \
                 : "=r"(r0), "=r"(r1), "=r"(r2), "=r"(r3) : "r"(addr))

// ---------------- setup kernels ----------------
__global__ void detect_idx_kernel(const int* e) {
    if (threadIdx.x == 0 && blockIdx.x == 0) {
        int is64 = 1;
        for (int k = 0; k < 128; k++) {
            if (e[2 * k + 1] != 0) { is64 = 0; break; }
        }
        g_idx64 = is64;
    }
}

__global__ void zero2_int_kernel() {
    int i = blockIdx.x * blockDim.x + threadIdx.x;
    if (i < NN) { g_cnti[i] = 0; g_fill[i] = 0; }
}

__global__ void count_kernel(const void* eidx) {
    int e = blockIdx.x * blockDim.x + threadIdx.x;
    if (e >= NE) return;
    int d;
    if (g_idx64) d = (int)((const long long*)eidx)[(long long)NE + e];
    else         d = ((const int*)eidx)[NE + e];
    atomicAdd(&g_cnti[d], 1);
}

__global__ void scan_kernel() {
    __shared__ int part[1024];
    const int t = threadIdx.x;
    const int CH = 20;
    const int base = t * CH;
    int s = 0;
    for (int i = 0; i < CH; i++) {
        int idx = base + i;
        if (idx < NN) s += g_cnti[idx];
    }
    part[t] = s;
    __syncthreads();
    for (int off = 1; off < 1024; off <<= 1) {
        int v = 0;
        if (t >= off) v = part[t - off];
        __syncthreads();
        part[t] += v;
        __syncthreads();
    }
    int run = (t == 0) ? 0 : part[t - 1];
    for (int i = 0; i < CH; i++) {
        int idx = base + i;
        if (idx < NN) { g_rowptr[idx] = run; run += g_cnti[idx]; }
    }
    if (t == 1023) g_rowptr[NN] = part[1023];
}

__global__ void fill_kernel(const void* eidx, const float* __restrict__ pos) {
    int e = blockIdx.x * blockDim.x + threadIdx.x;
    if (e >= NE) return;
    int s, d;
    if (g_idx64) {
        s = (int)((const long long*)eidx)[e];
        d = (int)((const long long*)eidx)[(long long)NE + e];
    } else {
        s = ((const int*)eidx)[e];
        d = ((const int*)eidx)[NE + e];
    }
    int p = g_rowptr[d] + atomicAdd(&g_fill[d], 1);
    g_esrc[p] = s;
    g_erel[p] = make_float2(pos[2 * s] - pos[2 * d], pos[2 * s + 1] - pos[2 * d + 1]);
}

__global__ void make_inv_kernel() {
    int i = blockIdx.x * blockDim.x + threadIdx.x;
    if (i < NN) {
        int c = g_rowptr[i + 1] - g_rowptr[i];
        g_inv[i] = (c > 0) ? (1.f / (float)c) : 0.f;
    }
}

// W[K][N] fp32 -> WT[N][Kp] fp16 (zero-fill k in [Kreal, Kp))
__global__ void trconv_kernel(const float* __restrict__ src, __half* __restrict__ dst,
                              int Kreal, int N, int Kp)
{
    __shared__ float tile[32][33];
    const int bx = blockIdx.x * 32;  // n
    const int by = blockIdx.y * 32;  // k
    const int x = threadIdx.x, y = threadIdx.y;
    for (int i = 0; i < 32; i += 8) {
        int k = by + y + i, n = bx + x;
        tile[y + i][x] = (k < Kreal && n < N) ? src[(size_t)k * N + n] : 0.f;
    }
    __syncthreads();
    for (int i = 0; i < 32; i += 8) {
        int n = bx + y + i, k = by + x;
        if (n < N && k < Kp) dst[(size_t)n * Kp + k] = __float2half_rn(tile[x][y + i]);
    }
}

__global__ void convh_kernel(const float* __restrict__ h) {
    int idx = blockIdx.x * blockDim.x + threadIdx.x;
    if (idx >= NN * 16) return;
    int r = idx >> 4, c = idx & 15;
    g_h16[(size_t)r * 64 + c] = __float2half_rn(h[idx]);
}

// ---------------- fp16 MMA GEMM: 128x128 tile, BK=64, 3-stage, ONE sync/stage ----------------
#define HPITCHB 144                     // bytes per smem row (72 halves)
#define HASTG  (128 * HPITCHB)          // 18432
#define HBSTG  (128 * HPITCHB)          // 18432
#define HSTAGE (HASTG + HBSTG)          // 36864
#define HSMEM_BYTES (3 * HSTAGE)        // 110592 per CTA -> 2 CTAs/SM (221KB/SM)

__global__ void __launch_bounds__(256, 2)
hgemm_kernel(const __half* __restrict__ A, const __half* __restrict__ Bt,
             const float* __restrict__ bias, const float* __restrict__ rowscale,
             __half* __restrict__ C, int M, int N, int K, int doRelu)
{
    extern __shared__ char smemc[];
    const uint32_t sBase = (uint32_t)__cvta_generic_to_shared(smemc);

    const int tid = threadIdx.x;
    const int wid = tid >> 5, lane = tid & 31;
    const int wr = wid >> 2, wc = wid & 3;
    const int mW = wr * 64, nW = wc * 32;
    const int g = lane >> 2, t = lane & 3;
    const int q = lane >> 3, r = lane & 7;
    const int rowBase = blockIdx.y * 128;
    const int colBase = blockIdx.x * 128;
    const int nk = K >> 6;

    // A x4: m0=(rows0-7,k0-7) m1=(rows8-15,k0-7) m2=(rows0-7,k8-15) m3=(rows8-15,k8-15)
    const uint32_t aOff = (uint32_t)((mW + ((q & 1) << 3) + r) * HPITCHB + ((q >> 1) << 4));
    // B x4: m0=(n0-7,k0-7) m1=(n0-7,k8-15) m2=(n8-15,k0-7) m3=(n8-15,k8-15)
    const uint32_t bOff = (uint32_t)(HASTG + (nW + ((q >> 1) << 3) + r) * HPITCHB + ((q & 1) << 4));

    auto prefetch = [&](int s) {
        const uint32_t aB = sBase + (uint32_t)(s % 3) * HSTAGE;
        const uint32_t bB = aB + HASTG;
        const int k0 = s << 6;
#pragma unroll
        for (int i = 0; i < 4; i++) {           // A: 128 rows x 8 chunks of 16B
            int idx = tid + 256 * i;
            int rr = idx >> 3, ch = idx & 7;
            bool v = (rowBase + rr) < M;
            const __half* src = v ? (A + (size_t)(rowBase + rr) * K + k0 + ch * 8) : A;
            cp16(aB + (uint32_t)(rr * HPITCHB + ch * 16), src, v);
        }
#pragma unroll
        for (int i = 0; i < 4; i++) {           // B: 128 rows x 8 chunks
            int idx = tid + 256 * i;
            int rr = idx >> 3, ch = idx & 7;
            const __half* src = Bt + (size_t)(colBase + rr) * K + k0 + ch * 8;
            cp16(bB + (uint32_t)(rr * HPITCHB + ch * 16), src, true);
        }
        asm volatile("cp.async.commit_group;");
    };

    float acc[4][4][4];
#pragma unroll
    for (int a = 0; a < 4; a++)
#pragma unroll
        for (int b = 0; b < 4; b++)
#pragma unroll
            for (int c = 0; c < 4; c++) acc[a][b][c] = 0.f;

    prefetch(0);
    if (1 < nk) prefetch(1);

    for (int s = 0; s < nk; s++) {
        if (s + 1 < nk) asm volatile("cp.async.wait_group 1;");
        else            asm volatile("cp.async.wait_group 0;");
        __syncthreads();
        // Safe: buffer (s+2)%3 was last READ in iteration s-1; all warps passed
        // this iteration's barrier, so those reads are complete. Readers of
        // stage s+2 sit behind that stage's own wait+barrier.
        if (s + 2 < nk) prefetch(s + 2);

        const uint32_t stg = sBase + (uint32_t)(s % 3) * HSTAGE;

#pragma unroll
        for (int kk = 0; kk < 4; kk++) {
            uint32_t af[4][4];
#pragma unroll
            for (int mt = 0; mt < 4; mt++)
                LDSM_X4(af[mt][0], af[mt][1], af[mt][2], af[mt][3],
                        stg + aOff + (uint32_t)(mt * 16 * HPITCHB + kk * 32));
            uint32_t bf[4][2];
#pragma unroll
            for (int np = 0; np < 2; np++)
                LDSM_X4(bf[2 * np][0], bf[2 * np][1], bf[2 * np + 1][0], bf[2 * np + 1][1],
                        stg + bOff + (uint32_t)(np * 16 * HPITCHB + kk * 32));
#pragma unroll
            for (int mt = 0; mt < 4; mt++)
#pragma unroll
                for (int nt = 0; nt < 4; nt++)
                    asm volatile(
                        "mma.sync.aligned.m16n8k16.row.col.f32.f16.f16.f32 "
                        "{%0,%1,%2,%3}, {%4,%5,%6,%7}, {%8,%9}, {%0,%1,%2,%3};"
                        : "+f"(acc[mt][nt][0]), "+f"(acc[mt][nt][1]),
                          "+f"(acc[mt][nt][2]), "+f"(acc[mt][nt][3])
                        : "r"(af[mt][0]), "r"(af[mt][1]), "r"(af[mt][2]), "r"(af[mt][3]),
                          "r"(bf[nt][0]), "r"(bf[nt][1]));
        }
        // no trailing __syncthreads: next iteration's wait+barrier protects reuse
    }

    // epilogue: c0=(g,2t) c1=(g,2t+1) c2=(g+8,2t) c3=(g+8,2t+1)
#pragma unroll
    for (int mt = 0; mt < 4; mt++) {
        const int r0 = rowBase + mW + mt * 16 + g;
#pragma unroll
        for (int half = 0; half < 2; half++) {
            const int rr = r0 + half * 8;
            if (rr >= M) continue;
            const float rs = rowscale ? rowscale[rr] : 1.f;
            const bool masked = (rowscale != nullptr) && (rs == 0.f);
#pragma unroll
            for (int nt = 0; nt < 4; nt++) {
                const int c = colBase + nW + nt * 8 + 2 * t;
                float v0 = acc[mt][nt][half * 2 + 0] * rs + bias[c];
                float v1 = acc[mt][nt][half * 2 + 1] * rs + bias[c + 1];
                if (doRelu) { v0 = fmaxf(v0, 0.f); v1 = fmaxf(v1, 0.f); }
                if (masked) { v0 = 0.f; v1 = 0.f; }
                __half2 hv = __floats2half2_rn(v0, v1);
                *(uint32_t*)(C + (size_t)rr * N + c) = *(uint32_t*)&hv;
            }
        }
    }
}

// ---------------- CSR gather-aggregate: 4 cols/lane (H=128/256) ----------------
__global__ void aggregate_kernel(const __half* __restrict__ t,
                                 const float* __restrict__ wpos,
                                 __half* __restrict__ out, int H, int cbShift)
{
    const int warpGlobal = (blockIdx.x * blockDim.x + threadIdx.x) >> 5;
    const int lane = threadIdx.x & 31;
    const int node = warpGlobal >> cbShift;
    if (node >= NN) return;
    const int cb = warpGlobal & ((1 << cbShift) - 1);
    const int col = cb * 128 + lane * 4;

    const float4 wx = *(const float4*)(wpos + col);
    const float4 wy = *(const float4*)(wpos + H + col);

    const int beg = g_rowptr[node];
    const int end = g_rowptr[node + 1];

    float4 acc = make_float4(0.f, 0.f, 0.f, 0.f);

    for (int b = beg; b < end; b += 32) {
        const int n = min(32, end - b);
        int sj = 0;
        float rxj = 0.f, ryj = 0.f;
        if (b + lane < end) {
            sj = g_esrc[b + lane];
            float2 rr = g_erel[b + lane];
            rxj = rr.x; ryj = rr.y;
        }
#pragma unroll 4
        for (int j = 0; j < n; j++) {
            const int s = __shfl_sync(0xFFFFFFFFu, sj, j);
            const float rx = __shfl_sync(0xFFFFFFFFu, rxj, j);
            const float ry = __shfl_sync(0xFFFFFFFFu, ryj, j);
            uint2 tv = *(const uint2*)(t + (size_t)s * H + col);
            float2 f0 = __half22float2(*reinterpret_cast<__half2*>(&tv.x));
            float2 f1 = __half22float2(*reinterpret_cast<__half2*>(&tv.y));
            acc.x += fmaxf(fmaf(rx, wx.x, fmaf(ry, wy.x, f0.x)), 0.f);
            acc.y += fmaxf(fmaf(rx, wx.y, fmaf(ry, wy.y, f0.y)), 0.f);
            acc.z += fmaxf(fmaf(rx, wx.z, fmaf(ry, wy.z, f1.x)), 0.f);
            acc.w += fmaxf(fmaf(rx, wx.w, fmaf(ry, wy.w, f1.y)), 0.f);
        }
    }
    __half2 h0 = __floats2half2_rn(acc.x, acc.y);
    __half2 h1 = __floats2half2_rn(acc.z, acc.w);
    uint2 o;
    o.x = *(uint32_t*)&h0;
    o.y = *(uint32_t*)&h1;
    *(uint2*)(out + (size_t)node * H + col) = o;
}

// ---------------- CSR gather-aggregate: 8 cols/lane, H=1024 fixed ----------------
__global__ void aggregate8_kernel(const __half* __restrict__ t,
                                  const float* __restrict__ wpos,
                                  __half* __restrict__ out)
{
    const int warpGlobal = (blockIdx.x * blockDim.x + threadIdx.x) >> 5;
    const int lane = threadIdx.x & 31;
    const int node = warpGlobal >> 2;
    if (node >= NN) return;
    const int cb = warpGlobal & 3;
    const int col = cb * 256 + lane * 8;

    const float4 wx0 = *(const float4*)(wpos + col);
    const float4 wx1 = *(const float4*)(wpos + col + 4);
    const float4 wy0 = *(const float4*)(wpos + 1024 + col);
    const float4 wy1 = *(const float4*)(wpos + 1024 + col + 4);

    const int beg = g_rowptr[node];
    const int end = g_rowptr[node + 1];

    float a0 = 0.f, a1 = 0.f, a2 = 0.f, a3 = 0.f;
    float a4 = 0.f, a5 = 0.f, a6 = 0.f, a7 = 0.f;

    for (int b = beg; b < end; b += 32) {
        const int n = min(32, end - b);
        int sj = 0;
        float rxj = 0.f, ryj = 0.f;
        if (b + lane < end) {
            sj = g_esrc[b + lane];
            float2 rr = g_erel[b + lane];
            rxj = rr.x; ryj = rr.y;
        }
#pragma unroll 4
        for (int j = 0; j < n; j++) {
            const int s = __shfl_sync(0xFFFFFFFFu, sj, j);
            const float rx = __shfl_sync(0xFFFFFFFFu, rxj, j);
            const float ry = __shfl_sync(0xFFFFFFFFu, ryj, j);
            uint4 tv = *(const uint4*)(t + (size_t)s * 1024 + col);
            float2 f0 = __half22float2(*reinterpret_cast<__half2*>(&tv.x));
            float2 f1 = __half22float2(*reinterpret_cast<__half2*>(&tv.y));
            float2 f2 = __half22float2(*reinterpret_cast<__half2*>(&tv.z));
            float2 f3 = __half22float2(*reinterpret_cast<__half2*>(&tv.w));
            a0 += fmaxf(fmaf(rx, wx0.x, fmaf(ry, wy0.x, f0.x)), 0.f);
            a1 += fmaxf(fmaf(rx, wx0.y, fmaf(ry, wy0.y, f0.y)), 0.f);
            a2 += fmaxf(fmaf(rx, wx0.z, fmaf(ry, wy0.z, f1.x)), 0.f);
            a3 += fmaxf(fmaf(rx, wx0.w, fmaf(ry, wy0.w, f1.y)), 0.f);
            a4 += fmaxf(fmaf(rx, wx1.x, fmaf(ry, wy1.x, f2.x)), 0.f);
            a5 += fmaxf(fmaf(rx, wx1.y, fmaf(ry, wy1.y, f2.y)), 0.f);
            a6 += fmaxf(fmaf(rx, wx1.z, fmaf(ry, wy1.z, f3.x)), 0.f);
            a7 += fmaxf(fmaf(rx, wx1.w, fmaf(ry, wy1.w, f3.y)), 0.f);
        }
    }
    __half2 h0 = __floats2half2_rn(a0, a1);
    __half2 h1 = __floats2half2_rn(a2, a3);
    __half2 h2 = __floats2half2_rn(a4, a5);
    __half2 h3 = __floats2half2_rn(a6, a7);
    uint4 o;
    o.x = *(uint32_t*)&h0; o.y = *(uint32_t*)&h1;
    o.z = *(uint32_t*)&h2; o.w = *(uint32_t*)&h3;
    *(uint4*)(out + (size_t)node * 1024 + col) = o;
}

// ---------------- final head GEMM (N=4), fp16 A ----------------
__global__ void headN4_kernel(const __half* __restrict__ A, const float* __restrict__ W,
                              const float* __restrict__ b, float* __restrict__ out)
{
    const int warp = (blockIdx.x * blockDim.x + threadIdx.x) >> 5;
    const int lane = threadIdx.x & 31;
    if (warp >= NN) return;
    const __half* ar = A + (size_t)warp * 512;
    float s0 = 0.f, s1 = 0.f, s2 = 0.f, s3 = 0.f;
    for (int k = lane; k < 512; k += 32) {
        const float a = __half2float(ar[k]);
        const float4 w = *(const float4*)(W + k * 4);
        s0 = fmaf(a, w.x, s0); s1 = fmaf(a, w.y, s1);
        s2 = fmaf(a, w.z, s2); s3 = fmaf(a, w.w, s3);
    }
#pragma unroll
    for (int o = 16; o; o >>= 1) {
        s0 += __shfl_down_sync(0xFFFFFFFFu, s0, o);
        s1 += __shfl_down_sync(0xFFFFFFFFu, s1, o);
        s2 += __shfl_down_sync(0xFFFFFFFFu, s2, o);
        s3 += __shfl_down_sync(0xFFFFFFFFu, s3, o);
    }
    if (lane == 0)
        *(float4*)(out + (size_t)warp * 4) =
            make_float4(s0 + b[0], s1 + b[1], s2 + b[2], s3 + b[3]);
}

// ---------------- host helpers ----------------
static inline void run_hgemm(const __half* A, const __half* Bt, const float* bias,
                             const float* rowscale, __half* C, int M, int N, int K, int doRelu)
{
    dim3 grid(N / 128, (M + 127) / 128);
    hgemm_kernel<<<grid, 256, HSMEM_BYTES>>>(A, Bt, bias, rowscale, C, M, N, K, doRelu);
}

static inline void run_agg(const __half* t, const float* wpos, __half* s, int H, int cbShift)
{
    const long long threads = ((long long)NN << cbShift) * 32;
    aggregate_kernel<<<(unsigned)((threads + 255) / 256), 256>>>(t, wpos, s, H, cbShift);
}

static inline void run_agg8(const __half* t, const float* wpos, __half* s)
{
    const long long threads = (long long)NN * 4 * 32;
    aggregate8_kernel<<<(unsigned)((threads + 255) / 256), 256>>>(t, wpos, s);
}

static inline void run_trc_s(cudaStream_t st, const float* src, __half* dst,
                             int Kreal, int N, int Kp)
{
    trconv_kernel<<<dim3((N + 31) / 32, (Kreal + 31) / 32), dim3(32, 8), 0, st>>>(
        src, dst, Kreal, N, Kp);
}

extern "C" void kernel_launch(void* const* d_in, const int* in_sizes, int n_in,
                              void* d_out, int out_size)
{
    const float* h    = (const float*)d_in[0];
    const float* pos  = (const float*)d_in[1];
    const void*  eidx = d_in[2];

    const float* l1_w1 = (const float*)d_in[3];
    const float* l1_b1 = (const float*)d_in[4];
    const float* l1_w2 = (const float*)d_in[5];
    const float* l1_b2 = (const float*)d_in[6];
    const float* l2_w1 = (const float*)d_in[7];
    const float* l2_b1 = (const float*)d_in[8];
    const float* l2_w2 = (const float*)d_in[9];
    const float* l2_b2 = (const float*)d_in[10];
    const float* l3_w1 = (const float*)d_in[11];
    const float* l3_b1 = (const float*)d_in[12];
    const float* l3_w2 = (const float*)d_in[13];
    const float* l3_b2 = (const float*)d_in[14];
    const float* l4_w1 = (const float*)d_in[15];
    const float* l4_b1 = (const float*)d_in[16];
    const float* l4_w2 = (const float*)d_in[17];
    const float* l4_b2 = (const float*)d_in[18];
    const float* hd_w1 = (const float*)d_in[19];
    const float* hd_b1 = (const float*)d_in[20];
    const float* hd_w2 = (const float*)d_in[21];
    const float* hd_b2 = (const float*)d_in[22];
    const float* hd_w3 = (const float*)d_in[23];
    const float* hd_b3 = (const float*)d_in[24];

    __half *hA, *hB, *hC, *h16, *w16;
    float* inv;
    cudaGetSymbolAddress((void**)&hA, g_hA);
    cudaGetSymbolAddress((void**)&hB, g_hB);
    cudaGetSymbolAddress((void**)&hC, g_hC);
    cudaGetSymbolAddress((void**)&h16, g_h16);
    cudaGetSymbolAddress((void**)&w16, g_w16);
    cudaGetSymbolAddress((void**)&inv, g_inv);

    cudaFuncSetAttribute(hgemm_kernel,
                         cudaFuncAttributeMaxDynamicSharedMemorySize, HSMEM_BYTES);

    // side stream + events (created once; reused across calls)
    static cudaStream_t s1 = nullptr;
    static cudaEvent_t evF = nullptr, evCSR = nullptr, evW = nullptr;
    if (s1 == nullptr) {
        cudaStreamCreateWithFlags(&s1, cudaStreamNonBlocking);
        cudaEventCreateWithFlags(&evF, cudaEventDisableTiming);
        cudaEventCreateWithFlags(&evCSR, cudaEventDisableTiming);
        cudaEventCreateWithFlags(&evW, cudaEventDisableTiming);
    }

    // fork s1 off the main stream
    cudaEventRecord(evF, 0);
    cudaStreamWaitEvent(s1, evF, 0);

    // s1: CSR build
    detect_idx_kernel<<<1, 32, 0, s1>>>((const int*)d_in[2]);
    zero2_int_kernel<<<(NN + 255) / 256, 256, 0, s1>>>();
    count_kernel<<<(NE + 255) / 256, 256, 0, s1>>>(eidx);
    scan_kernel<<<1, 1024, 0, s1>>>();
    fill_kernel<<<(NE + 255) / 256, 256, 0, s1>>>(eidx, pos);
    make_inv_kernel<<<(NN + 255) / 256, 256, 0, s1>>>();
    cudaEventRecord(evCSR, s1);

    // s1: weight transposes for layers 2..head
    run_trc_s(s1, l2_w1, w16 + O_L2W1, 128, 256, 128);
    run_trc_s(s1, l2_w2, w16 + O_L2W2, 256, 256, 256);
    run_trc_s(s1, l3_w1, w16 + O_L3W1, 256, 1024, 256);
    run_trc_s(s1, l3_w2, w16 + O_L3W2, 1024, 1024, 1024);
    run_trc_s(s1, l4_w1, w16 + O_L4W1, 1024, 1024, 1024);
    run_trc_s(s1, l4_w2, w16 + O_L4W2, 1024, 1024, 1024);
    run_trc_s(s1, hd_w1, w16 + O_HDW1, 1024, 1024, 1024);
    run_trc_s(s1, hd_w2, w16 + O_HDW2, 1024, 512, 1024);
    cudaEventRecord(evW, s1);

    // main stream: layer-1 prep + GEMM1 (overlaps with s1)
    convh_kernel<<<(NN * 16 + 255) / 256, 256>>>(h);
    run_trc_s(0, l1_w1, w16 + O_L1W1, 16, 128, 64);
    run_trc_s(0, l1_w2, w16 + O_L1W2, 128, 128, 128);
    run_hgemm(h16, w16 + O_L1W1, l1_b1, nullptr, hB, NN, 128, 64, 0);

    // join CSR before aggregation
    cudaStreamWaitEvent(0, evCSR, 0);
    run_agg(hB, l1_w1 + (size_t)16 * 128, hC, 128, 0);
    run_hgemm(hC, w16 + O_L1W2, l1_b2, inv, hA, NN, 128, 128, 1);

    // join weights before layer 2
    cudaStreamWaitEvent(0, evW, 0);

    // --- layer 2: 128 -> 256 -> 256 ---
    run_hgemm(hA, w16 + O_L2W1, l2_b1, nullptr, hB, NN, 256, 128, 0);
    run_agg(hB, l2_w1 + (size_t)128 * 256, hC, 256, 1);
    run_hgemm(hC, w16 + O_L2W2, l2_b2, inv, hA, NN, 256, 256, 1);

    // --- layer 3: 256 -> 1024 -> 1024 ---
    run_hgemm(hA, w16 + O_L3W1, l3_b1, nullptr, hB, NN, 1024, 256, 0);
    run_agg8(hB, l3_w1 + (size_t)256 * 1024, hC);
    run_hgemm(hC, w16 + O_L3W2, l3_b2, inv, hA, NN, 1024, 1024, 1);

    // --- layer 4: 1024 -> 1024 -> 1024 ---
    run_hgemm(hA, w16 + O_L4W1, l4_b1, nullptr, hB, NN, 1024, 1024, 0);
    run_agg8(hB, l4_w1 + (size_t)1024 * 1024, hC);
    run_hgemm(hC, w16 + O_L4W2, l4_b2, inv, hA, NN, 1024, 1024, 1);

    // --- head MLP ---
    run_hgemm(hA, w16 + O_HDW1, hd_b1, nullptr, hB, NN, 1024, 1024, 1);
    run_hgemm(hB, w16 + O_HDW2, hd_b2, nullptr, hC, NN, 512, 1024, 1);
    headN4_kernel<<<(NN * 32 + 255) / 256, 256>>>(hC, hd_w3, hd_b3, (float*)d_out);
}

// round 15
// speedup vs baseline: 1.0335x; 1.0012x over previous
#include <cuda_runtime.h>
#include <cuda_fp16.h>
#include <stdint.h>

#define NN 20000
#define NE 320000

// ---------------- static scratch (BSS zero-init gives free zero padding) ----------------
__device__ __half g_hA[(size_t)NN * 1024];
__device__ __half g_hB[(size_t)NN * 1024];
__device__ __half g_hC[(size_t)NN * 1024];
__device__ __half g_h16[(size_t)NN * 64];      // h padded 16 -> 64 cols
__device__ __half g_w16[5128192];              // transposed fp16 weights
__device__ float g_inv[NN];
__device__ int   g_cnti[NN];
__device__ int   g_fill[NN];
__device__ int   g_rowptr[NN + 1];
__device__ int   g_esrc[NE];
__device__ float2 g_erel[NE];
__device__ int   g_idx64;

// transposed fp16 weight offsets (halves). [Np][Kp] layouts.
#define O_L1W1 0          // 256 x 64   (real 128 x 16)
#define O_L1W2 16384      // 256 x 128
#define O_L2W1 49152      // 256 x 128
#define O_L2W2 81920      // 256 x 256
#define O_L3W1 147456     // 1024 x 256
#define O_L3W2 409600     // 1024 x 1024
#define O_L4W1 1458176
#define O_L4W2 2506752
#define O_HDW1 3555328
#define O_HDW2 4603904    // 512 x 1024

__device__ __forceinline__ void cp16(uint32_t dst, const void* src, bool v) {
    if (v)
        asm volatile("cp.async.cg.shared.global [%0], [%1], 16;" :: "r"(dst), "l"(src));
    else
        asm volatile("cp.async.cg.shared.global [%0], [%1], 16, 0;" :: "r"(dst), "l"(src));
}

#define LDSM_X4(r0, r1, r2, r3, addr) \
    asm volatile("ldmatrix.sync.aligned.m8n8.x4.shared.b16 {%0,%1,%2,%3}, [%4];" \
                 : "=r"(r0), "=r"(r1), "=r"(r2), "=r"(r3) : "r"(addr))

// ---------------- setup kernels ----------------
__global__ void detect_idx_kernel(const int* e) {
    if (threadIdx.x == 0 && blockIdx.x == 0) {
        int is64 = 1;
        for (int k = 0; k < 128; k++) {
            if (e[2 * k + 1] != 0) { is64 = 0; break; }
        }
        g_idx64 = is64;
    }
}

__global__ void zero2_int_kernel() {
    int i = blockIdx.x * blockDim.x + threadIdx.x;
    if (i < NN) { g_cnti[i] = 0; g_fill[i] = 0; }
}

__global__ void count_kernel(const void* eidx) {
    int e = blockIdx.x * blockDim.x + threadIdx.x;
    if (e >= NE) return;
    int d;
    if (g_idx64) d = (int)((const long long*)eidx)[(long long)NE + e];
    else         d = ((const int*)eidx)[NE + e];
    atomicAdd(&g_cnti[d], 1);
}

__global__ void scan_kernel() {
    __shared__ int part[1024];
    const int t = threadIdx.x;
    const int CH = 20;
    const int base = t * CH;
    int s = 0;
    for (int i = 0; i < CH; i++) {
        int idx = base + i;
        if (idx < NN) s += g_cnti[idx];
    }
    part[t] = s;
    __syncthreads();
    for (int off = 1; off < 1024; off <<= 1) {
        int v = 0;
        if (t >= off) v = part[t - off];
        __syncthreads();
        part[t] += v;
        __syncthreads();
    }
    int run = (t == 0) ? 0 : part[t - 1];
    for (int i = 0; i < CH; i++) {
        int idx = base + i;
        if (idx < NN) { g_rowptr[idx] = run; run += g_cnti[idx]; }
    }
    if (t == 1023) g_rowptr[NN] = part[1023];
}

__global__ void fill_kernel(const void* eidx, const float* __restrict__ pos) {
    int e = blockIdx.x * blockDim.x + threadIdx.x;
    if (e >= NE) return;
    int s, d;
    if (g_idx64) {
        s = (int)((const long long*)eidx)[e];
        d = (int)((const long long*)eidx)[(long long)NE + e];
    } else {
        s = ((const int*)eidx)[e];
        d = ((const int*)eidx)[NE + e];
    }
    int p = g_rowptr[d] + atomicAdd(&g_fill[d], 1);
    g_esrc[p] = s;
    g_erel[p] = make_float2(pos[2 * s] - pos[2 * d], pos[2 * s + 1] - pos[2 * d + 1]);
}

__global__ void make_inv_kernel() {
    int i = blockIdx.x * blockDim.x + threadIdx.x;
    if (i < NN) {
        int c = g_rowptr[i + 1] - g_rowptr[i];
        g_inv[i] = (c > 0) ? (1.f / (float)c) : 0.f;
    }
}

// W[K][N] fp32 -> WT[N][Kp] fp16 (zero-fill k in [Kreal, Kp))
__global__ void trconv_kernel(const float* __restrict__ src, __half* __restrict__ dst,
                              int Kreal, int N, int Kp)
{
    __shared__ float tile[32][33];
    const int bx = blockIdx.x * 32;  // n
    const int by = blockIdx.y * 32;  // k
    const int x = threadIdx.x, y = threadIdx.y;
    for (int i = 0; i < 32; i += 8) {
        int k = by + y + i, n = bx + x;
        tile[y + i][x] = (k < Kreal && n < N) ? src[(size_t)k * N + n] : 0.f;
    }
    __syncthreads();
    for (int i = 0; i < 32; i += 8) {
        int n = bx + y + i, k = by + x;
        if (n < N && k < Kp) dst[(size_t)n * Kp + k] = __float2half_rn(tile[x][y + i]);
    }
}

__global__ void convh_kernel(const float* __restrict__ h) {
    int idx = blockIdx.x * blockDim.x + threadIdx.x;
    if (idx >= NN * 16) return;
    int r = idx >> 4, c = idx & 15;
    g_h16[(size_t)r * 64 + c] = __float2half_rn(h[idx]);
}

// ---------------- fp16 MMA GEMM: 128x128 tile, BK=64, 3-stage, ONE sync/stage ----------------
#define HPITCHB 144                     // bytes per smem row (72 halves)
#define HASTG  (128 * HPITCHB)          // 18432
#define HBSTG  (128 * HPITCHB)          // 18432
#define HSTAGE (HASTG + HBSTG)          // 36864
#define HSMEM_BYTES (3 * HSTAGE)        // 110592 per CTA -> 2 CTAs/SM (221KB/SM)

__global__ void __launch_bounds__(256, 2)
hgemm_kernel(const __half* __restrict__ A, const __half* __restrict__ Bt,
             const float* __restrict__ bias, const float* __restrict__ rowscale,
             __half* __restrict__ C, int M, int N, int K, int doRelu)
{
    extern __shared__ char smemc[];
    const uint32_t sBase = (uint32_t)__cvta_generic_to_shared(smemc);

    const int tid = threadIdx.x;
    const int wid = tid >> 5, lane = tid & 31;
    const int wr = wid >> 2, wc = wid & 3;
    const int mW = wr * 64, nW = wc * 32;
    const int g = lane >> 2, t = lane & 3;
    const int q = lane >> 3, r = lane & 7;
    const int rowBase = blockIdx.y * 128;
    const int colBase = blockIdx.x * 128;
    const int nk = K >> 6;

    // A x4: m0=(rows0-7,k0-7) m1=(rows8-15,k0-7) m2=(rows0-7,k8-15) m3=(rows8-15,k8-15)
    const uint32_t aOff = (uint32_t)((mW + ((q & 1) << 3) + r) * HPITCHB + ((q >> 1) << 4));
    // B x4: m0=(n0-7,k0-7) m1=(n0-7,k8-15) m2=(n8-15,k0-7) m3=(n8-15,k8-15)
    const uint32_t bOff = (uint32_t)(HASTG + (nW + ((q >> 1) << 3) + r) * HPITCHB + ((q & 1) << 4));

    auto prefetch = [&](int s) {
        const uint32_t aB = sBase + (uint32_t)(s % 3) * HSTAGE;
        const uint32_t bB = aB + HASTG;
        const int k0 = s << 6;
#pragma unroll
        for (int i = 0; i < 4; i++) {           // A: 128 rows x 8 chunks of 16B
            int idx = tid + 256 * i;
            int rr = idx >> 3, ch = idx & 7;
            bool v = (rowBase + rr) < M;
            const __half* src = v ? (A + (size_t)(rowBase + rr) * K + k0 + ch * 8) : A;
            cp16(aB + (uint32_t)(rr * HPITCHB + ch * 16), src, v);
        }
#pragma unroll
        for (int i = 0; i < 4; i++) {           // B: 128 rows x 8 chunks
            int idx = tid + 256 * i;
            int rr = idx >> 3, ch = idx & 7;
            const __half* src = Bt + (size_t)(colBase + rr) * K + k0 + ch * 8;
            cp16(bB + (uint32_t)(rr * HPITCHB + ch * 16), src, true);
        }
        asm volatile("cp.async.commit_group;");
    };

    float acc[4][4][4];
#pragma unroll
    for (int a = 0; a < 4; a++)
#pragma unroll
        for (int b = 0; b < 4; b++)
#pragma unroll
            for (int c = 0; c < 4; c++) acc[a][b][c] = 0.f;

    prefetch(0);
    if (1 < nk) prefetch(1);

    for (int s = 0; s < nk; s++) {
        if (s + 1 < nk) asm volatile("cp.async.wait_group 1;");
        else            asm volatile("cp.async.wait_group 0;");
        __syncthreads();
        // Safe: buffer (s+2)%3 was last READ in iteration s-1; all warps passed
        // this iteration's barrier, so those reads are complete. Readers of
        // stage s+2 sit behind that stage's own wait+barrier.
        if (s + 2 < nk) prefetch(s + 2);

        const uint32_t stg = sBase + (uint32_t)(s % 3) * HSTAGE;

#pragma unroll
        for (int kk = 0; kk < 4; kk++) {
            uint32_t af[4][4];
#pragma unroll
            for (int mt = 0; mt < 4; mt++)
                LDSM_X4(af[mt][0], af[mt][1], af[mt][2], af[mt][3],
                        stg + aOff + (uint32_t)(mt * 16 * HPITCHB + kk * 32));
            uint32_t bf[4][2];
#pragma unroll
            for (int np = 0; np < 2; np++)
                LDSM_X4(bf[2 * np][0], bf[2 * np][1], bf[2 * np + 1][0], bf[2 * np + 1][1],
                        stg + bOff + (uint32_t)(np * 16 * HPITCHB + kk * 32));
#pragma unroll
            for (int mt = 0; mt < 4; mt++)
#pragma unroll
                for (int nt = 0; nt < 4; nt++)
                    asm volatile(
                        "mma.sync.aligned.m16n8k16.row.col.f32.f16.f16.f32 "
                        "{%0,%1,%2,%3}, {%4,%5,%6,%7}, {%8,%9}, {%0,%1,%2,%3};"
                        : "+f"(acc[mt][nt][0]), "+f"(acc[mt][nt][1]),
                          "+f"(acc[mt][nt][2]), "+f"(acc[mt][nt][3])
                        : "r"(af[mt][0]), "r"(af[mt][1]), "r"(af[mt][2]), "r"(af[mt][3]),
                          "r"(bf[nt][0]), "r"(bf[nt][1]));
        }
        // no trailing __syncthreads: next iteration's wait+barrier protects reuse
    }

    // epilogue: c0=(g,2t) c1=(g,2t+1) c2=(g+8,2t) c3=(g+8,2t+1)
#pragma unroll
    for (int mt = 0; mt < 4; mt++) {
        const int r0 = rowBase + mW + mt * 16 + g;
#pragma unroll
        for (int half = 0; half < 2; half++) {
            const int rr = r0 + half * 8;
            if (rr >= M) continue;
            const float rs = rowscale ? rowscale[rr] : 1.f;
            const bool masked = (rowscale != nullptr) && (rs == 0.f);
#pragma unroll
            for (int nt = 0; nt < 4; nt++) {
                const int c = colBase + nW + nt * 8 + 2 * t;
                float v0 = acc[mt][nt][half * 2 + 0] * rs + bias[c];
                float v1 = acc[mt][nt][half * 2 + 1] * rs + bias[c + 1];
                if (doRelu) { v0 = fmaxf(v0, 0.f); v1 = fmaxf(v1, 0.f); }
                if (masked) { v0 = 0.f; v1 = 0.f; }
                __half2 hv = __floats2half2_rn(v0, v1);
                *(uint32_t*)(C + (size_t)rr * N + c) = *(uint32_t*)&hv;
            }
        }
    }
}

// ---------------- CSR gather-aggregate: 4 cols/lane (H=128/256) ----------------
__global__ void aggregate_kernel(const __half* __restrict__ t,
                                 const float* __restrict__ wpos,
                                 __half* __restrict__ out, int H, int cbShift)
{
    const int warpGlobal = (blockIdx.x * blockDim.x + threadIdx.x) >> 5;
    const int lane = threadIdx.x & 31;
    const int node = warpGlobal >> cbShift;
    if (node >= NN) return;
    const int cb = warpGlobal & ((1 << cbShift) - 1);
    const int col = cb * 128 + lane * 4;

    const float4 wx = *(const float4*)(wpos + col);
    const float4 wy = *(const float4*)(wpos + H + col);

    const int beg = g_rowptr[node];
    const int end = g_rowptr[node + 1];

    float4 acc = make_float4(0.f, 0.f, 0.f, 0.f);

    for (int b = beg; b < end; b += 32) {
        const int n = min(32, end - b);
        int sj = 0;
        float rxj = 0.f, ryj = 0.f;
        if (b + lane < end) {
            sj = g_esrc[b + lane];
            float2 rr = g_erel[b + lane];
            rxj = rr.x; ryj = rr.y;
        }
#pragma unroll 4
        for (int j = 0; j < n; j++) {
            const int s = __shfl_sync(0xFFFFFFFFu, sj, j);
            const float rx = __shfl_sync(0xFFFFFFFFu, rxj, j);
            const float ry = __shfl_sync(0xFFFFFFFFu, ryj, j);
            uint2 tv = *(const uint2*)(t + (size_t)s * H + col);
            float2 f0 = __half22float2(*reinterpret_cast<__half2*>(&tv.x));
            float2 f1 = __half22float2(*reinterpret_cast<__half2*>(&tv.y));
            acc.x += fmaxf(fmaf(rx, wx.x, fmaf(ry, wy.x, f0.x)), 0.f);
            acc.y += fmaxf(fmaf(rx, wx.y, fmaf(ry, wy.y, f0.y)), 0.f);
            acc.z += fmaxf(fmaf(rx, wx.z, fmaf(ry, wy.z, f1.x)), 0.f);
            acc.w += fmaxf(fmaf(rx, wx.w, fmaf(ry, wy.w, f1.y)), 0.f);
        }
    }
    __half2 h0 = __floats2half2_rn(acc.x, acc.y);
    __half2 h1 = __floats2half2_rn(acc.z, acc.w);
    uint2 o;
    o.x = *(uint32_t*)&h0;
    o.y = *(uint32_t*)&h1;
    *(uint2*)(out + (size_t)node * H + col) = o;
}

// ---------------- CSR gather-aggregate: 8 cols/lane, H=1024 fixed ----------------
__global__ void aggregate8_kernel(const __half* __restrict__ t,
                                  const float* __restrict__ wpos,
                                  __half* __restrict__ out)
{
    const int warpGlobal = (blockIdx.x * blockDim.x + threadIdx.x) >> 5;
    const int lane = threadIdx.x & 31;
    const int node = warpGlobal >> 2;
    if (node >= NN) return;
    const int cb = warpGlobal & 3;
    const int col = cb * 256 + lane * 8;

    const float4 wx0 = *(const float4*)(wpos + col);
    const float4 wx1 = *(const float4*)(wpos + col + 4);
    const float4 wy0 = *(const float4*)(wpos + 1024 + col);
    const float4 wy1 = *(const float4*)(wpos + 1024 + col + 4);

    const int beg = g_rowptr[node];
    const int end = g_rowptr[node + 1];

    float a0 = 0.f, a1 = 0.f, a2 = 0.f, a3 = 0.f;
    float a4 = 0.f, a5 = 0.f, a6 = 0.f, a7 = 0.f;

    for (int b = beg; b < end; b += 32) {
        const int n = min(32, end - b);
        int sj = 0;
        float rxj = 0.f, ryj = 0.f;
        if (b + lane < end) {
            sj = g_esrc[b + lane];
            float2 rr = g_erel[b + lane];
            rxj = rr.x; ryj = rr.y;
        }
#pragma unroll 4
        for (int j = 0; j < n; j++) {
            const int s = __shfl_sync(0xFFFFFFFFu, sj, j);
            const float rx = __shfl_sync(0xFFFFFFFFu, rxj, j);
            const float ry = __shfl_sync(0xFFFFFFFFu, ryj, j);
            uint4 tv = *(const uint4*)(t + (size_t)s * 1024 + col);
            float2 f0 = __half22float2(*reinterpret_cast<__half2*>(&tv.x));
            float2 f1 = __half22float2(*reinterpret_cast<__half2*>(&tv.y));
            float2 f2 = __half22float2(*reinterpret_cast<__half2*>(&tv.z));
            float2 f3 = __half22float2(*reinterpret_cast<__half2*>(&tv.w));
            a0 += fmaxf(fmaf(rx, wx0.x, fmaf(ry, wy0.x, f0.x)), 0.f);
            a1 += fmaxf(fmaf(rx, wx0.y, fmaf(ry, wy0.y, f0.y)), 0.f);
            a2 += fmaxf(fmaf(rx, wx0.z, fmaf(ry, wy0.z, f1.x)), 0.f);
            a3 += fmaxf(fmaf(rx, wx0.w, fmaf(ry, wy0.w, f1.y)), 0.f);
            a4 += fmaxf(fmaf(rx, wx1.x, fmaf(ry, wy1.x, f2.x)), 0.f);
            a5 += fmaxf(fmaf(rx, wx1.y, fmaf(ry, wy1.y, f2.y)), 0.f);
            a6 += fmaxf(fmaf(rx, wx1.z, fmaf(ry, wy1.z, f3.x)), 0.f);
            a7 += fmaxf(fmaf(rx, wx1.w, fmaf(ry, wy1.w, f3.y)), 0.f);
        }
    }
    __half2 h0 = __floats2half2_rn(a0, a1);
    __half2 h1 = __floats2half2_rn(a2, a3);
    __half2 h2 = __floats2half2_rn(a4, a5);
    __half2 h3 = __floats2half2_rn(a6, a7);
    uint4 o;
    o.x = *(uint32_t*)&h0; o.y = *(uint32_t*)&h1;
    o.z = *(uint32_t*)&h2; o.w = *(uint32_t*)&h3;
    *(uint4*)(out + (size_t)node * 1024 + col) = o;
}

// ---------------- final head GEMM (N=4), fp16 A ----------------
__global__ void headN4_kernel(const __half* __restrict__ A, const float* __restrict__ W,
                              const float* __restrict__ b, float* __restrict__ out)
{
    const int warp = (blockIdx.x * blockDim.x + threadIdx.x) >> 5;
    const int lane = threadIdx.x & 31;
    if (warp >= NN) return;
    const __half* ar = A + (size_t)warp * 512;
    float s0 = 0.f, s1 = 0.f, s2 = 0.f, s3 = 0.f;
    for (int k = lane; k < 512; k += 32) {
        const float a = __half2float(ar[k]);
        const float4 w = *(const float4*)(W + k * 4);
        s0 = fmaf(a, w.x, s0); s1 = fmaf(a, w.y, s1);
        s2 = fmaf(a, w.z, s2); s3 = fmaf(a, w.w, s3);
    }
#pragma unroll
    for (int o = 16; o; o >>= 1) {
        s0 += __shfl_down_sync(0xFFFFFFFFu, s0, o);
        s1 += __shfl_down_sync(0xFFFFFFFFu, s1, o);
        s2 += __shfl_down_sync(0xFFFFFFFFu, s2, o);
        s3 += __shfl_down_sync(0xFFFFFFFFu, s3, o);
    }
    if (lane == 0)
        *(float4*)(out + (size_t)warp * 4) =
            make_float4(s0 + b[0], s1 + b[1], s2 + b[2], s3 + b[3]);
}

// ---------------- host helpers ----------------
static inline void run_hgemm(const __half* A, const __half* Bt, const float* bias,
                             const float* rowscale, __half* C, int M, int N, int K, int doRelu)
{
    dim3 grid(N / 128, (M + 127) / 128);
    hgemm_kernel<<<grid, 256, HSMEM_BYTES>>>(A, Bt, bias, rowscale, C, M, N, K, doRelu);
}

static inline void run_agg(const __half* t, const float* wpos, __half* s, int H, int cbShift)
{
    const long long threads = ((long long)NN << cbShift) * 32;
    aggregate_kernel<<<(unsigned)((threads + 255) / 256), 256>>>(t, wpos, s, H, cbShift);
}

static inline void run_agg8(const __half* t, const float* wpos, __half* s)
{
    const long long threads = (long long)NN * 4 * 32;
    aggregate8_kernel<<<(unsigned)((threads + 255) / 256), 256>>>(t, wpos, s);
}

static inline void run_trc_s(cudaStream_t st, const float* src, __half* dst,
                             int Kreal, int N, int Kp)
{
    trconv_kernel<<<dim3((N + 31) / 32, (Kreal + 31) / 32), dim3(32, 8), 0, st>>>(
        src, dst, Kreal, N, Kp);
}

extern "C" void kernel_launch(void* const* d_in, const int* in_sizes, int n_in,
                              void* d_out, int out_size)
{
    const float* h    = (const float*)d_in[0];
    const float* pos  = (const float*)d_in[1];
    const void*  eidx = d_in[2];

    const float* l1_w1 = (const float*)d_in[3];
    const float* l1_b1 = (const float*)d_in[4];
    const float* l1_w2 = (const float*)d_in[5];
    const float* l1_b2 = (const float*)d_in[6];
    const float* l2_w1 = (const float*)d_in[7];
    const float* l2_b1 = (const float*)d_in[8];
    const float* l2_w2 = (const float*)d_in[9];
    const float* l2_b2 = (const float*)d_in[10];
    const float* l3_w1 = (const float*)d_in[11];
    const float* l3_b1 = (const float*)d_in[12];
    const float* l3_w2 = (const float*)d_in[13];
    const float* l3_b2 = (const float*)d_in[14];
    const float* l4_w1 = (const float*)d_in[15];
    const float* l4_b1 = (const float*)d_in[16];
    const float* l4_w2 = (const float*)d_in[17];
    const float* l4_b2 = (const float*)d_in[18];
    const float* hd_w1 = (const float*)d_in[19];
    const float* hd_b1 = (const float*)d_in[20];
    const float* hd_w2 = (const float*)d_in[21];
    const float* hd_b2 = (const float*)d_in[22];
    const float* hd_w3 = (const float*)d_in[23];
    const float* hd_b3 = (const float*)d_in[24];

    __half *hA, *hB, *hC, *h16, *w16;
    float* inv;
    cudaGetSymbolAddress((void**)&hA, g_hA);
    cudaGetSymbolAddress((void**)&hB, g_hB);
    cudaGetSymbolAddress((void**)&hC, g_hC);
    cudaGetSymbolAddress((void**)&h16, g_h16);
    cudaGetSymbolAddress((void**)&w16, g_w16);
    cudaGetSymbolAddress((void**)&inv, g_inv);

    cudaFuncSetAttribute(hgemm_kernel,
                         cudaFuncAttributeMaxDynamicSharedMemorySize, HSMEM_BYTES);

    // side stream + events (created once; reused across calls)
    static cudaStream_t s1 = nullptr;
    static cudaEvent_t evF = nullptr, evCSR = nullptr, evW = nullptr;
    if (s1 == nullptr) {
        cudaStreamCreateWithFlags(&s1, cudaStreamNonBlocking);
        cudaEventCreateWithFlags(&evF, cudaEventDisableTiming);
        cudaEventCreateWithFlags(&evCSR, cudaEventDisableTiming);
        cudaEventCreateWithFlags(&evW, cudaEventDisableTiming);
    }

    // fork s1 off the main stream
    cudaEventRecord(evF, 0);
    cudaStreamWaitEvent(s1, evF, 0);

    // s1: CSR build
    detect_idx_kernel<<<1, 32, 0, s1>>>((const int*)d_in[2]);
    zero2_int_kernel<<<(NN + 255) / 256, 256, 0, s1>>>();
    count_kernel<<<(NE + 255) / 256, 256, 0, s1>>>(eidx);
    scan_kernel<<<1, 1024, 0, s1>>>();
    fill_kernel<<<(NE + 255) / 256, 256, 0, s1>>>(eidx, pos);
    make_inv_kernel<<<(NN + 255) / 256, 256, 0, s1>>>();
    cudaEventRecord(evCSR, s1);

    // s1: weight transposes for layers 2..head
    run_trc_s(s1, l2_w1, w16 + O_L2W1, 128, 256, 128);
    run_trc_s(s1, l2_w2, w16 + O_L2W2, 256, 256, 256);
    run_trc_s(s1, l3_w1, w16 + O_L3W1, 256, 1024, 256);
    run_trc_s(s1, l3_w2, w16 + O_L3W2, 1024, 1024, 1024);
    run_trc_s(s1, l4_w1, w16 + O_L4W1, 1024, 1024, 1024);
    run_trc_s(s1, l4_w2, w16 + O_L4W2, 1024, 1024, 1024);
    run_trc_s(s1, hd_w1, w16 + O_HDW1, 1024, 1024, 1024);
    run_trc_s(s1, hd_w2, w16 + O_HDW2, 1024, 512, 1024);
    cudaEventRecord(evW, s1);

    // main stream: layer-1 prep + GEMM1 (overlaps with s1)
    convh_kernel<<<(NN * 16 + 255) / 256, 256>>>(h);
    run_trc_s(0, l1_w1, w16 + O_L1W1, 16, 128, 64);
    run_trc_s(0, l1_w2, w16 + O_L1W2, 128, 128, 128);
    run_hgemm(h16, w16 + O_L1W1, l1_b1, nullptr, hB, NN, 128, 64, 0);

    // join CSR before aggregation
    cudaStreamWaitEvent(0, evCSR, 0);
    run_agg(hB, l1_w1 + (size_t)16 * 128, hC, 128, 0);
    run_hgemm(hC, w16 + O_L1W2, l1_b2, inv, hA, NN, 128, 128, 1);

    // join weights before layer 2
    cudaStreamWaitEvent(0, evW, 0);

    // --- layer 2: 128 -> 256 -> 256 ---
    run_hgemm(hA, w16 + O_L2W1, l2_b1, nullptr, hB, NN, 256, 128, 0);
    run_agg(hB, l2_w1 + (size_t)128 * 256, hC, 256, 1);
    run_hgemm(hC, w16 + O_L2W2, l2_b2, inv, hA, NN, 256, 256, 1);

    // --- layer 3: 256 -> 1024 -> 1024 ---
    run_hgemm(hA, w16 + O_L3W1, l3_b1, nullptr, hB, NN, 1024, 256, 0);
    run_agg8(hB, l3_w1 + (size_t)256 * 1024, hC);
    run_hgemm(hC, w16 + O_L3W2, l3_b2, inv, hA, NN, 1024, 1024, 1);

    // --- layer 4: 1024 -> 1024 -> 1024 ---
    run_hgemm(hA, w16 + O_L4W1, l4_b1, nullptr, hB, NN, 1024, 1024, 0);
    run_agg8(hB, l4_w1 + (size_t)1024 * 1024, hC);
    run_hgemm(hC, w16 + O_L4W2, l4_b2, inv, hA, NN, 1024, 1024, 1);

    // --- head MLP ---
    run_hgemm(hA, w16 + O_HDW1, hd_b1, nullptr, hB, NN, 1024, 1024, 1);
    run_hgemm(hB, w16 + O_HDW2, hd_b2, nullptr, hC, NN, 512, 1024, 1);
    headN4_kernel<<<(NN * 32 + 255) / 256, 256>>>(hC, hd_w3, hd_b3, (float*)d_out);
}